// round 1
// baseline (speedup 1.0000x reference)
#include <cuda_runtime.h>
#include <cuda_bf16.h>
#include <math.h>

#define B   2
#define T   2048
#define H   1024
#define NH  16
#define D   64
#define SCALE 0.125f   // D^-0.5 = 1/8

// ---------------- static device scratch (no dynamic allocation allowed) ----
__device__ float g_Q[(size_t)NH * B * T * D];     // 16 MB
__device__ float g_K[(size_t)NH * B * T * D];     // 16 MB
__device__ float g_V[(size_t)B * T * D];          // 1 MB
__device__ float g_W[(size_t)NH * B * T * T];     // 536 MB  per-head scores->weights
__device__ float g_MH[(size_t)B * T * D];         // 1 MB    mean head output

// ---------------------------------------------------------------------------
// Kernel 1: projections. grid = (T/64, 2*NH+1, B).
//   y <  NH      -> Q head y
//   y in [NH,2NH)-> K head y-NH
//   y == 2NH     -> V (shared)
// C[t,d] = sum_h x[b,t,h] * W[h,d] + bias[d]; M=T rows, K=H, N=D=64.
// ---------------------------------------------------------------------------
__global__ void proj_kernel(const float* __restrict__ x,
                            const float* __restrict__ Wq, const float* __restrict__ bq,
                            const float* __restrict__ Wk, const float* __restrict__ bk,
                            const float* __restrict__ Wv, const float* __restrict__ bv)
{
    const int t_tile = blockIdx.x;
    const int y      = blockIdx.y;
    const int b      = blockIdx.z;

    const float* Wm; const float* bias; float* C;
    if (y < NH) {
        Wm = Wq + (size_t)y * H * D;  bias = bq + y * D;
        C  = g_Q + (size_t)(y * B + b) * T * D;
    } else if (y < 2 * NH) {
        const int n = y - NH;
        Wm = Wk + (size_t)n * H * D;  bias = bk + n * D;
        C  = g_K + (size_t)(n * B + b) * T * D;
    } else {
        Wm = Wv;  bias = bv;
        C  = g_V + (size_t)b * T * D;
    }
    const float* A = x + (size_t)b * T * H;   // [T,H]

    __shared__ float As[64][17];
    __shared__ float Bs[16][65];

    const int tx = threadIdx.x, ty = threadIdx.y;
    const int tid = ty * 16 + tx;
    const int t0 = t_tile * 64;

    float acc[4][4];
#pragma unroll
    for (int i = 0; i < 4; i++)
#pragma unroll
        for (int j = 0; j < 4; j++) acc[i][j] = 0.f;

    for (int k0 = 0; k0 < H; k0 += 16) {
        // A tile: 64 x 16
#pragma unroll
        for (int i = 0; i < 4; i++) {
            int idx = tid + i * 256;
            int r = idx >> 4, c = idx & 15;
            As[r][c] = A[(size_t)(t0 + r) * H + k0 + c];
        }
        // B tile: 16 x 64
#pragma unroll
        for (int i = 0; i < 4; i++) {
            int idx = tid + i * 256;
            int r = idx >> 6, c = idx & 63;
            Bs[r][c] = Wm[(size_t)(k0 + r) * D + c];
        }
        __syncthreads();
#pragma unroll
        for (int kk = 0; kk < 16; kk++) {
            float a[4], bb[4];
#pragma unroll
            for (int i = 0; i < 4; i++) a[i]  = As[ty * 4 + i][kk];
#pragma unroll
            for (int j = 0; j < 4; j++) bb[j] = Bs[kk][tx * 4 + j];
#pragma unroll
            for (int i = 0; i < 4; i++)
#pragma unroll
                for (int j = 0; j < 4; j++) acc[i][j] += a[i] * bb[j];
        }
        __syncthreads();
    }
#pragma unroll
    for (int i = 0; i < 4; i++) {
        const int t = t0 + ty * 4 + i;
#pragma unroll
        for (int j = 0; j < 4; j++) {
            const int d = tx * 4 + j;
            C[(size_t)t * D + d] = acc[i][j] + bias[d];
        }
    }
}

// ---------------------------------------------------------------------------
// Kernel 2: raw scores (causal tiles only). grid = (32, 32, NH*B).
// S[t,s] = SCALE * dot(q[t,:], k[s,:]) for tiles with s_tile <= t_tile.
// Upper-triangular elements inside diagonal tiles are written but never read.
// ---------------------------------------------------------------------------
__global__ void scores_kernel()
{
    const int s_tile = blockIdx.x;
    const int t_tile = blockIdx.y;
    if (s_tile > t_tile) return;
    const int nb = blockIdx.z;

    const float* Qp = g_Q + (size_t)nb * T * D;
    const float* Kp = g_K + (size_t)nb * T * D;
    float*       Wp = g_W + (size_t)nb * T * T;

    __shared__ float Qs[64][65];
    __shared__ float Ks[64][65];

    const int tx = threadIdx.x, ty = threadIdx.y;
    const int tid = ty * 16 + tx;
    const int t0 = t_tile * 64, s0 = s_tile * 64;

#pragma unroll
    for (int i = 0; i < 16; i++) {
        int idx = tid + i * 256;
        int r = idx >> 6, c = idx & 63;
        Qs[r][c] = Qp[(size_t)(t0 + r) * D + c];
        Ks[r][c] = Kp[(size_t)(s0 + r) * D + c];
    }
    __syncthreads();

    float acc[4][4];
#pragma unroll
    for (int i = 0; i < 4; i++)
#pragma unroll
        for (int j = 0; j < 4; j++) acc[i][j] = 0.f;

#pragma unroll 8
    for (int kk = 0; kk < 64; kk++) {
        float a[4], bb[4];
#pragma unroll
        for (int i = 0; i < 4; i++) a[i]  = Qs[ty * 4 + i][kk];
#pragma unroll
        for (int j = 0; j < 4; j++) bb[j] = Ks[tx * 4 + j][kk];
#pragma unroll
        for (int i = 0; i < 4; i++)
#pragma unroll
            for (int j = 0; j < 4; j++) acc[i][j] += a[i] * bb[j];
    }

#pragma unroll
    for (int i = 0; i < 4; i++)
#pragma unroll
        for (int j = 0; j < 4; j++)
            Wp[(size_t)(t0 + ty * 4 + i) * T + s0 + tx * 4 + j] = acc[i][j] * SCALE;
}

// ---------------------------------------------------------------------------
// Kernel 3: in-place row softmax over valid prefix [0, t]. One block per row.
// grid = NH*B*T blocks, 256 threads.
// ---------------------------------------------------------------------------
__global__ void softmax_kernel()
{
    const int row = blockIdx.x;            // nb*T + t
    const int nb  = row >> 11;              // T = 2048
    const int t   = row & 2047;
    float* Wrow = g_W + (size_t)nb * T * T + (size_t)t * T;
    const int len = t + 1;
    const int tid = threadIdx.x;

    __shared__ float red[256];

    float m = -1e30f;
    for (int s = tid; s < len; s += 256) m = fmaxf(m, Wrow[s]);
    red[tid] = m; __syncthreads();
    for (int off = 128; off; off >>= 1) {
        if (tid < off) red[tid] = fmaxf(red[tid], red[tid + off]);
        __syncthreads();
    }
    m = red[0]; __syncthreads();

    float sum = 0.f;
    for (int s = tid; s < len; s += 256) sum += __expf(Wrow[s] - m);
    red[tid] = sum; __syncthreads();
    for (int off = 128; off; off >>= 1) {
        if (tid < off) red[tid] += red[tid + off];
        __syncthreads();
    }
    const float inv = 1.0f / red[0];

    for (int s = tid; s < len; s += 256)
        Wrow[s] = __expf(Wrow[s] - m) * inv;
}

// ---------------------------------------------------------------------------
// Kernel 4: mean over heads -> d_out mean_weights region. Deterministic
// (no atomics). Writes zeros above the diagonal. grid = B*T blocks.
// ---------------------------------------------------------------------------
__global__ void mean_kernel(float* __restrict__ out_mean)
{
    const int row = blockIdx.x;   // b*T + t
    const int b = row >> 11;
    const int t = row & 2047;
    float* mrow = out_mean + (size_t)row * T;
    for (int s = threadIdx.x; s < T; s += blockDim.x) {
        float acc = 0.f;
        if (s <= t) {
#pragma unroll
            for (int n = 0; n < NH; n++)
                acc += g_W[((size_t)(n * B + b) * T + t) * T + s];
            acc *= (1.0f / NH);
        }
        mrow[s] = acc;
    }
}

// ---------------------------------------------------------------------------
// Kernel 5: mean_head = (1/NH) sum_n (W_n @ V), causal. grid = (T/64, B).
// Output tile 64 t-rows x 64 d-cols, loop s-tiles (outer) then heads (inner).
// ---------------------------------------------------------------------------
__global__ void av_kernel()
{
    const int t_tile = blockIdx.x;
    const int b      = blockIdx.y;
    const int t0 = t_tile * 64;

    __shared__ float Ws[64][65];
    __shared__ float Vs[64][65];

    const int tx = threadIdx.x, ty = threadIdx.y;
    const int tid = ty * 16 + tx;

    float acc[4][4];
#pragma unroll
    for (int i = 0; i < 4; i++)
#pragma unroll
        for (int j = 0; j < 4; j++) acc[i][j] = 0.f;

    for (int st = 0; st <= t_tile; st++) {
        const int s0 = st * 64;
        // V tile (shared across heads)
#pragma unroll
        for (int i = 0; i < 16; i++) {
            int idx = tid + i * 256;
            int r = idx >> 6, c = idx & 63;
            Vs[r][c] = g_V[((size_t)b * T + s0 + r) * D + c];
        }
        const bool diag = (st == t_tile);
        for (int n = 0; n < NH; n++) {
            const float* Wp = g_W + (size_t)(n * B + b) * T * T;
            __syncthreads();
#pragma unroll
            for (int i = 0; i < 16; i++) {
                int idx = tid + i * 256;
                int r = idx >> 6, c = idx & 63;
                float v = 0.f;
                if (!diag || (s0 + c) <= (t0 + r))
                    v = Wp[(size_t)(t0 + r) * T + s0 + c];
                Ws[r][c] = v;
            }
            __syncthreads();
#pragma unroll 8
            for (int kk = 0; kk < 64; kk++) {
                float a[4], bb[4];
#pragma unroll
                for (int i = 0; i < 4; i++) a[i]  = Ws[ty * 4 + i][kk];
#pragma unroll
                for (int j = 0; j < 4; j++) bb[j] = Vs[kk][tx * 4 + j];
#pragma unroll
                for (int i = 0; i < 4; i++)
#pragma unroll
                    for (int j = 0; j < 4; j++) acc[i][j] += a[i] * bb[j];
            }
        }
        __syncthreads();
    }

#pragma unroll
    for (int i = 0; i < 4; i++)
#pragma unroll
        for (int j = 0; j < 4; j++)
            g_MH[((size_t)b * T + t0 + ty * 4 + i) * D + tx * 4 + j] =
                acc[i][j] * (1.0f / NH);
}

// ---------------------------------------------------------------------------
// Kernel 6: out = mean_head @ Wo + bo. M = B*T = 4096, K = D = 64, N = H.
// grid = (H/64, B*T/64).
// ---------------------------------------------------------------------------
__global__ void out_kernel(const float* __restrict__ Wo,
                           const float* __restrict__ bo,
                           float* __restrict__ out)
{
    const int n_tile = blockIdx.x;
    const int m_tile = blockIdx.y;
    const int n0 = n_tile * 64, m0 = m_tile * 64;

    __shared__ float As[64][65];
    __shared__ float Bs[64][65];

    const int tx = threadIdx.x, ty = threadIdx.y;
    const int tid = ty * 16 + tx;

#pragma unroll
    for (int i = 0; i < 16; i++) {
        int idx = tid + i * 256;
        int r = idx >> 6, c = idx & 63;
        As[r][c] = g_MH[(size_t)(m0 + r) * D + c];
        Bs[r][c] = Wo[(size_t)r * H + n0 + c];
    }
    __syncthreads();

    float acc[4][4];
#pragma unroll
    for (int i = 0; i < 4; i++)
#pragma unroll
        for (int j = 0; j < 4; j++) acc[i][j] = 0.f;

#pragma unroll 8
    for (int kk = 0; kk < 64; kk++) {
        float a[4], bb[4];
#pragma unroll
        for (int i = 0; i < 4; i++) a[i]  = As[ty * 4 + i][kk];
#pragma unroll
        for (int j = 0; j < 4; j++) bb[j] = Bs[kk][tx * 4 + j];
#pragma unroll
        for (int i = 0; i < 4; i++)
#pragma unroll
            for (int j = 0; j < 4; j++) acc[i][j] += a[i] * bb[j];
    }

#pragma unroll
    for (int i = 0; i < 4; i++)
#pragma unroll
        for (int j = 0; j < 4; j++)
            out[(size_t)(m0 + ty * 4 + i) * H + n0 + tx * 4 + j] =
                acc[i][j] + bo[n0 + tx * 4 + j];
}

// ---------------------------------------------------------------------------
extern "C" void kernel_launch(void* const* d_in, const int* in_sizes, int n_in,
                              void* d_out, int out_size)
{
    const float* x  = (const float*)d_in[0];
    const float* Wq = (const float*)d_in[1];
    const float* bq = (const float*)d_in[2];
    const float* Wk = (const float*)d_in[3];
    const float* bk = (const float*)d_in[4];
    const float* Wv = (const float*)d_in[5];
    const float* bv = (const float*)d_in[6];
    const float* Wo = (const float*)d_in[7];
    const float* bo = (const float*)d_in[8];

    float* out      = (float*)d_out;                       // [B,T,H]
    float* mean_out = out + (size_t)B * T * H;             // [B,T,T]

    dim3 blk(16, 16);

    proj_kernel   <<<dim3(T / 64, 2 * NH + 1, B), blk>>>(x, Wq, bq, Wk, bk, Wv, bv);
    scores_kernel <<<dim3(T / 64, T / 64, NH * B), blk>>>();
    softmax_kernel<<<NH * B * T, 256>>>();
    mean_kernel   <<<B * T, 256>>>(mean_out);
    av_kernel     <<<dim3(T / 64, B), blk>>>();
    out_kernel    <<<dim3(H / 64, (B * T) / 64), blk>>>(Wo, bo, out);
}

// round 2
// speedup vs baseline: 3.6271x; 3.6271x over previous
#include <cuda_runtime.h>
#include <cuda_bf16.h>
#include <math.h>

#define B    2
#define T    2048
#define H    1024
#define NH   16
#define D    64
#define SCALE 0.125f   // D^-0.5

// ---------------- static device scratch (no dynamic allocation allowed) ----
// Q,K layout: [B*T, NH*D] row-major (row = b*T+t, col = n*64+d)
__device__ float g_Q[(size_t)B * T * H];          // 16 MB
__device__ float g_K[(size_t)B * T * H];          // 16 MB
__device__ float g_V[(size_t)B * T * D];          // 1 MB
__device__ float g_W[(size_t)NH * B * T * T];     // 536 MB per-head weights
__device__ float g_MHp[(size_t)4 * B * T * D];    // 4 MB  AV partials (4 s-chunks)

// ---------------------------------------------------------------------------
// Kernel 1: batched Q/K projection.  C[4096,1024] = x[4096,1024] @ Wbig + bias
// Wbig(h, col) = W[(col>>6)*H*D + h*64 + (col&63)]   (col = n*64+d)
// bias[col] = b[col]  (bq/bk are [NH,D] contiguous = flat 1024)
// grid = (1024/128, 4096/128, 2)   z: 0 -> Q, 1 -> K
// ---------------------------------------------------------------------------
__global__ void __launch_bounds__(256, 2)
qkproj_kernel(const float* __restrict__ x,
              const float* __restrict__ Wq, const float* __restrict__ bq,
              const float* __restrict__ Wk, const float* __restrict__ bk)
{
    const float* Wm   = blockIdx.z ? Wk : Wq;
    const float* bias = blockIdx.z ? bk : bq;
    float*       C    = blockIdx.z ? g_K : g_Q;

    const int n0 = blockIdx.x * 128;
    const int m0 = blockIdx.y * 128;

    __shared__ float As[8][128];
    __shared__ float Bs[8][128];

    const int tid = threadIdx.x;
    const int tx = tid & 15, ty = tid >> 4;

    float acc[8][8];
#pragma unroll
    for (int i = 0; i < 8; i++)
#pragma unroll
        for (int j = 0; j < 8; j++) acc[i][j] = 0.f;

    const int ar  = tid >> 1;          // A row 0..127
    const int ac  = (tid & 1) * 4;     // A k-offset 0/4
    const int bkr = tid >> 5;          // B k-row 0..7
    const int bn  = (tid & 31) * 4;    // B col 0..124
    const int bcol = n0 + bn;
    const size_t bbase = (size_t)(bcol >> 6) * H * D + (size_t)(bcol & 63);

    for (int k0 = 0; k0 < H; k0 += 8) {
        float4 av = *(const float4*)&x[(size_t)(m0 + ar) * H + k0 + ac];
        As[ac + 0][ar] = av.x;
        As[ac + 1][ar] = av.y;
        As[ac + 2][ar] = av.z;
        As[ac + 3][ar] = av.w;
        float4 bv = *(const float4*)&Wm[bbase + (size_t)(k0 + bkr) * D];
        *(float4*)&Bs[bkr][bn] = bv;
        __syncthreads();
#pragma unroll
        for (int kk = 0; kk < 8; kk++) {
            float4 a0 = *(const float4*)&As[kk][ty * 4];
            float4 a1 = *(const float4*)&As[kk][ty * 4 + 64];
            float4 b0 = *(const float4*)&Bs[kk][tx * 4];
            float4 b1 = *(const float4*)&Bs[kk][tx * 4 + 64];
            float a[8]  = {a0.x, a0.y, a0.z, a0.w, a1.x, a1.y, a1.z, a1.w};
            float bb[8] = {b0.x, b0.y, b0.z, b0.w, b1.x, b1.y, b1.z, b1.w};
#pragma unroll
            for (int i = 0; i < 8; i++)
#pragma unroll
                for (int j = 0; j < 8; j++) acc[i][j] += a[i] * bb[j];
        }
        __syncthreads();
    }

#pragma unroll
    for (int ii = 0; ii < 2; ii++)
#pragma unroll
        for (int i = 0; i < 4; i++) {
            const int m = m0 + ii * 64 + ty * 4 + i;
#pragma unroll
            for (int jj = 0; jj < 2; jj++) {
                const int c = n0 + jj * 64 + tx * 4;
                float4 o;
                o.x = acc[ii * 4 + i][jj * 4 + 0] + bias[c + 0];
                o.y = acc[ii * 4 + i][jj * 4 + 1] + bias[c + 1];
                o.z = acc[ii * 4 + i][jj * 4 + 2] + bias[c + 2];
                o.w = acc[ii * 4 + i][jj * 4 + 3] + bias[c + 3];
                *(float4*)&C[(size_t)m * H + c] = o;
            }
        }
}

// ---------------------------------------------------------------------------
// Kernel 2: V projection. g_V[4096,64] = x @ Wv + bv. grid = B*T/64.
// ---------------------------------------------------------------------------
__global__ void vproj_kernel(const float* __restrict__ x,
                             const float* __restrict__ Wv,
                             const float* __restrict__ bv)
{
    const int m0 = blockIdx.x * 64;

    __shared__ float As[64][17];
    __shared__ float Bs[16][65];

    const int tx = threadIdx.x, ty = threadIdx.y;
    const int tid = ty * 16 + tx;

    float acc[4][4];
#pragma unroll
    for (int i = 0; i < 4; i++)
#pragma unroll
        for (int j = 0; j < 4; j++) acc[i][j] = 0.f;

    for (int k0 = 0; k0 < H; k0 += 16) {
#pragma unroll
        for (int i = 0; i < 4; i++) {
            int idx = tid + i * 256;
            int r = idx >> 4, c = idx & 15;
            As[r][c] = x[(size_t)(m0 + r) * H + k0 + c];
        }
#pragma unroll
        for (int i = 0; i < 4; i++) {
            int idx = tid + i * 256;
            int r = idx >> 6, c = idx & 63;
            Bs[r][c] = Wv[(size_t)(k0 + r) * D + c];
        }
        __syncthreads();
#pragma unroll
        for (int kk = 0; kk < 16; kk++) {
            float a[4], bb[4];
#pragma unroll
            for (int i = 0; i < 4; i++) a[i]  = As[ty * 4 + i][kk];
#pragma unroll
            for (int j = 0; j < 4; j++) bb[j] = Bs[kk][tx * 4 + j];
#pragma unroll
            for (int i = 0; i < 4; i++)
#pragma unroll
                for (int j = 0; j < 4; j++) acc[i][j] += a[i] * bb[j];
        }
        __syncthreads();
    }
#pragma unroll
    for (int i = 0; i < 4; i++)
#pragma unroll
        for (int j = 0; j < 4; j++)
            g_V[(size_t)(m0 + ty * 4 + i) * D + tx * 4 + j] =
                acc[i][j] + bv[tx * 4 + j];
}

// ---------------------------------------------------------------------------
// Kernel 3: raw scores (causal 128-tiles only). grid = (16, 16, NH*B).
// z = n*2 + b. S[t,s] = SCALE * dot(q,k). Upper-tri inside diag tiles is
// written but never read downstream.
// ---------------------------------------------------------------------------
__global__ void __launch_bounds__(256, 2)
scores_kernel()
{
    const int st = blockIdx.x;
    const int tt = blockIdx.y;
    if (st > tt) return;
    const int z = blockIdx.z;
    const int n = z >> 1, b = z & 1;

    const float* Qb = g_Q + (size_t)b * T * H + (size_t)n * D;
    const float* Kb = g_K + (size_t)b * T * H + (size_t)n * D;
    float*       Wp = g_W + (size_t)z * T * T;   // z == n*B+b

    const int t0 = tt * 128, s0 = st * 128;

    __shared__ float Qs[32][128];
    __shared__ float Ks[32][128];

    const int tid = threadIdx.x;
    const int tx = tid & 15, ty = tid >> 4;

    float acc[8][8];
#pragma unroll
    for (int i = 0; i < 8; i++)
#pragma unroll
        for (int j = 0; j < 8; j++) acc[i][j] = 0.f;

    const int lr = tid >> 1;           // row 0..127
    const int lc = (tid & 1) * 16;     // 16-col half within 32-chunk

    for (int kc = 0; kc < D; kc += 32) {
#pragma unroll
        for (int v = 0; v < 4; v++) {
            float4 q4 = *(const float4*)&Qb[(size_t)(t0 + lr) * H + kc + lc + v * 4];
            float4 k4 = *(const float4*)&Kb[(size_t)(s0 + lr) * H + kc + lc + v * 4];
            Qs[lc + v * 4 + 0][lr] = q4.x;
            Qs[lc + v * 4 + 1][lr] = q4.y;
            Qs[lc + v * 4 + 2][lr] = q4.z;
            Qs[lc + v * 4 + 3][lr] = q4.w;
            Ks[lc + v * 4 + 0][lr] = k4.x;
            Ks[lc + v * 4 + 1][lr] = k4.y;
            Ks[lc + v * 4 + 2][lr] = k4.z;
            Ks[lc + v * 4 + 3][lr] = k4.w;
        }
        __syncthreads();
#pragma unroll
        for (int kk = 0; kk < 32; kk++) {
            float4 a0 = *(const float4*)&Qs[kk][ty * 4];
            float4 a1 = *(const float4*)&Qs[kk][ty * 4 + 64];
            float4 b0 = *(const float4*)&Ks[kk][tx * 4];
            float4 b1 = *(const float4*)&Ks[kk][tx * 4 + 64];
            float a[8]  = {a0.x, a0.y, a0.z, a0.w, a1.x, a1.y, a1.z, a1.w};
            float bb[8] = {b0.x, b0.y, b0.z, b0.w, b1.x, b1.y, b1.z, b1.w};
#pragma unroll
            for (int i = 0; i < 8; i++)
#pragma unroll
                for (int j = 0; j < 8; j++) acc[i][j] += a[i] * bb[j];
        }
        __syncthreads();
    }

#pragma unroll
    for (int ii = 0; ii < 2; ii++)
#pragma unroll
        for (int i = 0; i < 4; i++) {
            const int t = t0 + ii * 64 + ty * 4 + i;
#pragma unroll
            for (int jj = 0; jj < 2; jj++) {
                const int s = s0 + jj * 64 + tx * 4;
                float4 o;
                o.x = acc[ii * 4 + i][jj * 4 + 0] * SCALE;
                o.y = acc[ii * 4 + i][jj * 4 + 1] * SCALE;
                o.z = acc[ii * 4 + i][jj * 4 + 2] * SCALE;
                o.w = acc[ii * 4 + i][jj * 4 + 3] * SCALE;
                *(float4*)&Wp[(size_t)t * T + s] = o;
            }
        }
}

// ---------------------------------------------------------------------------
// Kernel 4: in-place row softmax over prefix [0,t], single HBM read + write.
// Row buffered in smem. grid = NH*B*T, 256 threads.
// ---------------------------------------------------------------------------
__global__ void softmax_kernel()
{
    const int row = blockIdx.x;           // nb*T + t
    const int nb  = row >> 11;
    const int t   = row & 2047;
    float* Wrow = g_W + (size_t)nb * T * T + (size_t)t * T;
    const int len = t + 1;
    const int tid = threadIdx.x;
    const int lane = tid & 31, warp = tid >> 5;

    __shared__ float buf[T];
    __shared__ float red[8];

    float m = -1e30f;
    for (int s = tid; s < len; s += 256) {
        float v = Wrow[s];
        buf[s] = v;
        m = fmaxf(m, v);
    }
#pragma unroll
    for (int o = 16; o; o >>= 1) m = fmaxf(m, __shfl_xor_sync(0xffffffffu, m, o));
    if (lane == 0) red[warp] = m;
    __syncthreads();
    m = red[0];
#pragma unroll
    for (int w = 1; w < 8; w++) m = fmaxf(m, red[w]);
    __syncthreads();

    float sum = 0.f;
    for (int s = tid; s < len; s += 256) {
        float e = __expf(buf[s] - m);
        buf[s] = e;
        sum += e;
    }
#pragma unroll
    for (int o = 16; o; o >>= 1) sum += __shfl_xor_sync(0xffffffffu, sum, o);
    if (lane == 0) red[warp] = sum;
    __syncthreads();
    float tot = red[0];
#pragma unroll
    for (int w = 1; w < 8; w++) tot += red[w];
    const float inv = 1.0f / tot;

    for (int s = tid; s < len; s += 256) Wrow[s] = buf[s] * inv;
}

// ---------------------------------------------------------------------------
// Kernel 5: mean over heads -> mean_weights output (zeros above diagonal).
// grid = B*T.  Deterministic sum order.
// ---------------------------------------------------------------------------
__global__ void mean_kernel(float* __restrict__ out_mean)
{
    const int row = blockIdx.x;  // b*T + t
    const int b = row >> 11;
    const int t = row & 2047;
    float* mrow = out_mean + (size_t)row * T;
    for (int s = threadIdx.x; s < T; s += blockDim.x) {
        float acc = 0.f;
        if (s <= t) {
#pragma unroll
            for (int n = 0; n < NH; n++)
                acc += g_W[((size_t)(n * B + b) * T + t) * T + s];
            acc *= (1.0f / NH);
        }
        mrow[s] = acc;
    }
}

// ---------------------------------------------------------------------------
// Kernel 6: AV via the head-mean identity: mean_head = mean_weights @ V.
// Split over 4 s-chunks into partial buffers for parallelism.
// grid = (T/64, B, 4), block 16x16.
// ---------------------------------------------------------------------------
__global__ void av_kernel(const float* __restrict__ mean_w)
{
    const int t_tile = blockIdx.x;
    const int b      = blockIdx.y;
    const int chunk  = blockIdx.z;
    const int t0 = t_tile * 64;

    __shared__ float Ws[64][65];
    __shared__ float Vs[64][65];

    const int tx = threadIdx.x, ty = threadIdx.y;
    const int tid = ty * 16 + tx;

    float acc[4][4];
#pragma unroll
    for (int i = 0; i < 4; i++)
#pragma unroll
        for (int j = 0; j < 4; j++) acc[i][j] = 0.f;

    const int st_begin = chunk * 8;
    const int st_end   = min(chunk * 8 + 8, t_tile + 1);

    for (int st = st_begin; st < st_end; st++) {
        const int s0 = st * 64;
#pragma unroll
        for (int i = 0; i < 16; i++) {
            int idx = tid + i * 256;
            int r = idx >> 6, c = idx & 63;
            // mean_w has zeros above diag -> no masking needed
            Ws[r][c] = mean_w[((size_t)b * T + t0 + r) * T + s0 + c];
            Vs[r][c] = g_V[((size_t)b * T + s0 + r) * D + c];
        }
        __syncthreads();
#pragma unroll 8
        for (int kk = 0; kk < 64; kk++) {
            float a[4], bb[4];
#pragma unroll
            for (int i = 0; i < 4; i++) a[i]  = Ws[ty * 4 + i][kk];
#pragma unroll
            for (int j = 0; j < 4; j++) bb[j] = Vs[kk][tx * 4 + j];
#pragma unroll
            for (int i = 0; i < 4; i++)
#pragma unroll
                for (int j = 0; j < 4; j++) acc[i][j] += a[i] * bb[j];
        }
        __syncthreads();
    }

    float* Cp = g_MHp + (size_t)chunk * B * T * D;
#pragma unroll
    for (int i = 0; i < 4; i++)
#pragma unroll
        for (int j = 0; j < 4; j++)
            Cp[((size_t)b * T + t0 + ty * 4 + i) * D + tx * 4 + j] = acc[i][j];
}

// ---------------------------------------------------------------------------
// Kernel 7: out = (sum of AV partials) @ Wo + bo.  grid = (H/64, B*T/64).
// ---------------------------------------------------------------------------
__global__ void out_kernel(const float* __restrict__ Wo,
                           const float* __restrict__ bo,
                           float* __restrict__ out)
{
    const int n0 = blockIdx.x * 64;
    const int m0 = blockIdx.y * 64;

    __shared__ float As[64][65];
    __shared__ float Bs[64][65];

    const int tx = threadIdx.x, ty = threadIdx.y;
    const int tid = ty * 16 + tx;

#pragma unroll
    for (int i = 0; i < 16; i++) {
        int idx = tid + i * 256;
        int r = idx >> 6, c = idx & 63;
        size_t mi = (size_t)(m0 + r) * D + c;
        float v = g_MHp[mi] + g_MHp[(size_t)B * T * D + mi]
                + g_MHp[2 * (size_t)B * T * D + mi]
                + g_MHp[3 * (size_t)B * T * D + mi];
        As[r][c] = v;
        Bs[r][c] = Wo[(size_t)r * H + n0 + c];
    }
    __syncthreads();

    float acc[4][4];
#pragma unroll
    for (int i = 0; i < 4; i++)
#pragma unroll
        for (int j = 0; j < 4; j++) acc[i][j] = 0.f;

#pragma unroll 8
    for (int kk = 0; kk < 64; kk++) {
        float a[4], bb[4];
#pragma unroll
        for (int i = 0; i < 4; i++) a[i]  = As[ty * 4 + i][kk];
#pragma unroll
        for (int j = 0; j < 4; j++) bb[j] = Bs[kk][tx * 4 + j];
#pragma unroll
        for (int i = 0; i < 4; i++)
#pragma unroll
            for (int j = 0; j < 4; j++) acc[i][j] += a[i] * bb[j];
    }

#pragma unroll
    for (int i = 0; i < 4; i++)
#pragma unroll
        for (int j = 0; j < 4; j++)
            out[(size_t)(m0 + ty * 4 + i) * H + n0 + tx * 4 + j] =
                acc[i][j] + bo[n0 + tx * 4 + j];
}

// ---------------------------------------------------------------------------
extern "C" void kernel_launch(void* const* d_in, const int* in_sizes, int n_in,
                              void* d_out, int out_size)
{
    const float* x  = (const float*)d_in[0];
    const float* Wq = (const float*)d_in[1];
    const float* bq = (const float*)d_in[2];
    const float* Wk = (const float*)d_in[3];
    const float* bk = (const float*)d_in[4];
    const float* Wv = (const float*)d_in[5];
    const float* bv = (const float*)d_in[6];
    const float* Wo = (const float*)d_in[7];
    const float* bo = (const float*)d_in[8];

    float* out      = (float*)d_out;                 // [B,T,H]
    float* mean_out = out + (size_t)B * T * H;       // [B,T,T]

    dim3 blk16(16, 16);

    qkproj_kernel <<<dim3(H / 128, (B * T) / 128, 2), 256>>>(x, Wq, bq, Wk, bk);
    vproj_kernel  <<<(B * T) / 64, blk16>>>(x, Wv, bv);
    scores_kernel <<<dim3(T / 128, T / 128, NH * B), 256>>>();
    softmax_kernel<<<NH * B * T, 256>>>();
    mean_kernel   <<<B * T, 256>>>(mean_out);
    av_kernel     <<<dim3(T / 64, B, 4), blk16>>>(mean_out);
    out_kernel    <<<dim3(H / 64, (B * T) / 64), blk16>>>(Wo, bo, out);
}

// round 3
// speedup vs baseline: 5.8301x; 1.6074x over previous
#include <cuda_runtime.h>
#include <cuda_bf16.h>
#include <math.h>
#include <stdint.h>

#define B    2
#define T    2048
#define H    1024
#define NH   16
#define D    64
#define SCALE 0.125f   // D^-0.5

// ---------------- static device scratch (no dynamic allocation allowed) ----
// Q,K layout: [B*T, NH*D] row-major (row = b*T+t, col = n*64+d)
__device__ float g_Q[(size_t)B * T * H];          // 16 MB
__device__ float g_K[(size_t)B * T * H];          // 16 MB
__device__ float g_V[(size_t)B * T * D];          // 1 MB
__device__ float g_W[(size_t)NH * B * T * T];     // 536 MB raw scores (causal half valid)
__device__ float g_MHp[(size_t)4 * B * T * D];    // 4 MB AV partials

// ---------------------------------------------------------------------------
__device__ __forceinline__ uint32_t f2tf(float f) {
    uint32_t r;
    asm("cvt.rna.tf32.f32 %0, %1;" : "=r"(r) : "f"(f));
    return r;
}

__device__ __forceinline__ void mma_tf32(float* d, const uint32_t* a, const uint32_t* b) {
    asm volatile(
        "mma.sync.aligned.m16n8k8.row.col.f32.tf32.tf32.f32 "
        "{%0,%1,%2,%3}, {%4,%5,%6,%7}, {%8,%9}, {%0,%1,%2,%3};"
        : "+f"(d[0]), "+f"(d[1]), "+f"(d[2]), "+f"(d[3])
        : "r"(a[0]), "r"(a[1]), "r"(a[2]), "r"(a[3]), "r"(b[0]), "r"(b[1]));
}

// ---------------------------------------------------------------------------
// Kernel 1: batched Q/K projection with tf32 tensor cores.
// C[4096,1024] = x[4096,1024] @ Wbig + bias, Wbig(h,col)=W[(col>>6)*H*D+h*64+(col&63)].
// 128x128 CTA tile, 8 warps (2m x 4n), warp tile 64x32, BK=16, double buffered.
// grid = (8, 32, 2)  z: 0->Q, 1->K
// ---------------------------------------------------------------------------
__global__ void __launch_bounds__(256)
qkproj_tf32(const float* __restrict__ x,
            const float* __restrict__ Wq, const float* __restrict__ bq,
            const float* __restrict__ Wk, const float* __restrict__ bk)
{
    const float* Wm   = blockIdx.z ? Wk : Wq;
    const float* bias = blockIdx.z ? bk : bq;
    float*       C    = blockIdx.z ? g_K : g_Q;
    const int n0 = blockIdx.x * 128;
    const int m0 = blockIdx.y * 128;

    __shared__ uint32_t As[2][128][20];   // [m][k] pad 20 -> conflict-free frags
    __shared__ uint32_t Bs[2][16][136];   // [k][n] pad 136

    const int tid  = threadIdx.x;
    const int lane = tid & 31;
    const int wid  = tid >> 5;
    const int wm   = wid >> 2;          // 0..1
    const int wn   = wid & 3;           // 0..3
    const int fr   = lane >> 2;         // 0..7
    const int fc   = lane & 3;          // 0..3

    // staging assignments
    const int am  = tid >> 1;           // A row 0..127
    const int ak  = (tid & 1) * 8;      // A k-offset 0/8
    const int bkr = wid;                // B k-row 0..7 (and +8)
    const int bn  = lane * 4;           // B col 0..124
    const int bcol = n0 + bn;
    const size_t bbase = (size_t)(bcol >> 6) * (H * D) + (size_t)(bcol & 63);
    const float* xrow = x + (size_t)(m0 + am) * H + ak;

    float acc[4][4][4];
#pragma unroll
    for (int i = 0; i < 4; i++)
#pragma unroll
        for (int j = 0; j < 4; j++)
#pragma unroll
            for (int q = 0; q < 4; q++) acc[i][j][q] = 0.f;

    float4 ar0, ar1, br0, br1;

    // prologue: load iter 0
    ar0 = *(const float4*)&xrow[0];
    ar1 = *(const float4*)&xrow[4];
    br0 = *(const float4*)&Wm[bbase + (size_t)bkr * D];
    br1 = *(const float4*)&Wm[bbase + (size_t)(bkr + 8) * D];
    {
        uint4 u;
        u.x = f2tf(ar0.x); u.y = f2tf(ar0.y); u.z = f2tf(ar0.z); u.w = f2tf(ar0.w);
        *(uint4*)&As[0][am][ak] = u;
        u.x = f2tf(ar1.x); u.y = f2tf(ar1.y); u.z = f2tf(ar1.z); u.w = f2tf(ar1.w);
        *(uint4*)&As[0][am][ak + 4] = u;
        u.x = f2tf(br0.x); u.y = f2tf(br0.y); u.z = f2tf(br0.z); u.w = f2tf(br0.w);
        *(uint4*)&Bs[0][bkr][bn] = u;
        u.x = f2tf(br1.x); u.y = f2tf(br1.y); u.z = f2tf(br1.z); u.w = f2tf(br1.w);
        *(uint4*)&Bs[0][bkr + 8][bn] = u;
    }
    __syncthreads();

    const int NIT = H / 16;   // 64
    for (int it = 0; it < NIT; it++) {
        const int buf = it & 1;
        if (it < NIT - 1) {
            const int k0 = (it + 1) * 16;
            ar0 = *(const float4*)&xrow[k0];
            ar1 = *(const float4*)&xrow[k0 + 4];
            br0 = *(const float4*)&Wm[bbase + (size_t)(k0 + bkr) * D];
            br1 = *(const float4*)&Wm[bbase + (size_t)(k0 + bkr + 8) * D];
        }
#pragma unroll
        for (int ks = 0; ks < 2; ks++) {
            uint32_t af[4][4], bf[4][2];
#pragma unroll
            for (int tm = 0; tm < 4; tm++) {
                const int mb = wm * 64 + tm * 16;
                af[tm][0] = As[buf][mb + fr][ks * 8 + fc];
                af[tm][1] = As[buf][mb + fr + 8][ks * 8 + fc];
                af[tm][2] = As[buf][mb + fr][ks * 8 + fc + 4];
                af[tm][3] = As[buf][mb + fr + 8][ks * 8 + fc + 4];
            }
#pragma unroll
            for (int tn = 0; tn < 4; tn++) {
                const int nb = wn * 32 + tn * 8 + fr;
                bf[tn][0] = Bs[buf][ks * 8 + fc][nb];
                bf[tn][1] = Bs[buf][ks * 8 + fc + 4][nb];
            }
#pragma unroll
            for (int tm = 0; tm < 4; tm++)
#pragma unroll
                for (int tn = 0; tn < 4; tn++)
                    mma_tf32(acc[tm][tn], af[tm], bf[tn]);
        }
        if (it < NIT - 1) {
            const int nb2 = buf ^ 1;
            uint4 u;
            u.x = f2tf(ar0.x); u.y = f2tf(ar0.y); u.z = f2tf(ar0.z); u.w = f2tf(ar0.w);
            *(uint4*)&As[nb2][am][ak] = u;
            u.x = f2tf(ar1.x); u.y = f2tf(ar1.y); u.z = f2tf(ar1.z); u.w = f2tf(ar1.w);
            *(uint4*)&As[nb2][am][ak + 4] = u;
            u.x = f2tf(br0.x); u.y = f2tf(br0.y); u.z = f2tf(br0.z); u.w = f2tf(br0.w);
            *(uint4*)&Bs[nb2][bkr][bn] = u;
            u.x = f2tf(br1.x); u.y = f2tf(br1.y); u.z = f2tf(br1.z); u.w = f2tf(br1.w);
            *(uint4*)&Bs[nb2][bkr + 8][bn] = u;
        }
        __syncthreads();
    }

#pragma unroll
    for (int tm = 0; tm < 4; tm++)
#pragma unroll
        for (int tn = 0; tn < 4; tn++) {
            const int row = m0 + wm * 64 + tm * 16 + fr;
            const int col = n0 + wn * 32 + tn * 8 + 2 * fc;
            const float b0 = bias[col], b1 = bias[col + 1];
            float2 o;
            o.x = acc[tm][tn][0] + b0; o.y = acc[tm][tn][1] + b1;
            *(float2*)&C[(size_t)row * H + col] = o;
            o.x = acc[tm][tn][2] + b0; o.y = acc[tm][tn][3] + b1;
            *(float2*)&C[(size_t)(row + 8) * H + col] = o;
        }
}

// ---------------------------------------------------------------------------
// Kernel 2: V projection (fp32 SIMT, tiny). g_V = x @ Wv + bv. grid = B*T/64.
// ---------------------------------------------------------------------------
__global__ void vproj_kernel(const float* __restrict__ x,
                             const float* __restrict__ Wv,
                             const float* __restrict__ bv)
{
    const int m0 = blockIdx.x * 64;

    __shared__ float As[64][17];
    __shared__ float Bs[16][65];

    const int tx = threadIdx.x, ty = threadIdx.y;
    const int tid = ty * 16 + tx;

    float acc[4][4];
#pragma unroll
    for (int i = 0; i < 4; i++)
#pragma unroll
        for (int j = 0; j < 4; j++) acc[i][j] = 0.f;

    for (int k0 = 0; k0 < H; k0 += 16) {
#pragma unroll
        for (int i = 0; i < 4; i++) {
            int idx = tid + i * 256;
            int r = idx >> 4, c = idx & 15;
            As[r][c] = x[(size_t)(m0 + r) * H + k0 + c];
        }
#pragma unroll
        for (int i = 0; i < 4; i++) {
            int idx = tid + i * 256;
            int r = idx >> 6, c = idx & 63;
            Bs[r][c] = Wv[(size_t)(k0 + r) * D + c];
        }
        __syncthreads();
#pragma unroll
        for (int kk = 0; kk < 16; kk++) {
            float a[4], bb[4];
#pragma unroll
            for (int i = 0; i < 4; i++) a[i]  = As[ty * 4 + i][kk];
#pragma unroll
            for (int j = 0; j < 4; j++) bb[j] = Bs[kk][tx * 4 + j];
#pragma unroll
            for (int i = 0; i < 4; i++)
#pragma unroll
                for (int j = 0; j < 4; j++) acc[i][j] += a[i] * bb[j];
        }
        __syncthreads();
    }
#pragma unroll
    for (int i = 0; i < 4; i++)
#pragma unroll
        for (int j = 0; j < 4; j++)
            g_V[(size_t)(m0 + ty * 4 + i) * D + tx * 4 + j] =
                acc[i][j] + bv[tx * 4 + j];
}

// ---------------------------------------------------------------------------
// Kernel 3: raw scores via tf32 mma (causal 128-tiles only). grid=(16,16,32).
// z = n*2+b. Diagonal-tile upper-triangle is written but never read.
// ---------------------------------------------------------------------------
__global__ void __launch_bounds__(256)
scores_tf32()
{
    const int st = blockIdx.x;
    const int tt = blockIdx.y;
    if (st > tt) return;
    const int z = blockIdx.z;
    const int n = z >> 1, b = z & 1;

    const float* Qb = g_Q + (size_t)b * T * H + (size_t)n * D;
    const float* Kb = g_K + (size_t)b * T * H + (size_t)n * D;
    float*       Wp = g_W + (size_t)z * T * T;

    const int t0 = tt * 128, s0 = st * 128;

    __shared__ uint32_t Qs[128][36];   // [t][k] pad 36
    __shared__ uint32_t Ks[128][36];   // [s][k] pad 36

    const int tid  = threadIdx.x;
    const int lane = tid & 31;
    const int wid  = tid >> 5;
    const int wm   = wid >> 2;
    const int wn   = wid & 3;
    const int fr   = lane >> 2;
    const int fc   = lane & 3;

    const int sr = tid >> 1;           // 0..127
    const int sc = (tid & 1) * 16;     // 0/16

    float acc[4][4][4];
#pragma unroll
    for (int i = 0; i < 4; i++)
#pragma unroll
        for (int j = 0; j < 4; j++)
#pragma unroll
            for (int q = 0; q < 4; q++) acc[i][j][q] = 0.f;

    for (int kc = 0; kc < D; kc += 32) {
        if (kc) __syncthreads();
#pragma unroll
        for (int u = 0; u < 4; u++) {
            float4 q4 = *(const float4*)&Qb[(size_t)(t0 + sr) * H + kc + sc + u * 4];
            float4 k4 = *(const float4*)&Kb[(size_t)(s0 + sr) * H + kc + sc + u * 4];
            uint4 uq, uk;
            uq.x = f2tf(q4.x); uq.y = f2tf(q4.y); uq.z = f2tf(q4.z); uq.w = f2tf(q4.w);
            uk.x = f2tf(k4.x); uk.y = f2tf(k4.y); uk.z = f2tf(k4.z); uk.w = f2tf(k4.w);
            *(uint4*)&Qs[sr][sc + u * 4] = uq;
            *(uint4*)&Ks[sr][sc + u * 4] = uk;
        }
        __syncthreads();
#pragma unroll
        for (int ks = 0; ks < 4; ks++) {
            uint32_t af[4][4], bf[4][2];
#pragma unroll
            for (int tm = 0; tm < 4; tm++) {
                const int mb = wm * 64 + tm * 16;
                af[tm][0] = Qs[mb + fr][ks * 8 + fc];
                af[tm][1] = Qs[mb + fr + 8][ks * 8 + fc];
                af[tm][2] = Qs[mb + fr][ks * 8 + fc + 4];
                af[tm][3] = Qs[mb + fr + 8][ks * 8 + fc + 4];
            }
#pragma unroll
            for (int tn = 0; tn < 4; tn++) {
                const int nb = wn * 32 + tn * 8 + fr;
                bf[tn][0] = Ks[nb][ks * 8 + fc];
                bf[tn][1] = Ks[nb][ks * 8 + fc + 4];
            }
#pragma unroll
            for (int tm = 0; tm < 4; tm++)
#pragma unroll
                for (int tn = 0; tn < 4; tn++)
                    mma_tf32(acc[tm][tn], af[tm], bf[tn]);
        }
    }

#pragma unroll
    for (int tm = 0; tm < 4; tm++)
#pragma unroll
        for (int tn = 0; tn < 4; tn++) {
            const int t = t0 + wm * 64 + tm * 16 + fr;
            const int s = s0 + wn * 32 + tn * 8 + 2 * fc;
            float2 o;
            o.x = acc[tm][tn][0] * SCALE; o.y = acc[tm][tn][1] * SCALE;
            *(float2*)&Wp[(size_t)t * T + s] = o;
            o.x = acc[tm][tn][2] * SCALE; o.y = acc[tm][tn][3] * SCALE;
            *(float2*)&Wp[(size_t)(t + 8) * T + s] = o;
        }
}

// ---------------------------------------------------------------------------
// Kernel 4: FUSED per-head softmax + mean over heads. One block per (b,t).
// Row elements live in registers (<=8/thread). Reads g_W once (268MB causal),
// writes only mean_weights (33MB). grid = B*T, 256 threads.
// ---------------------------------------------------------------------------
__global__ void __launch_bounds__(256)
softmax_mean_kernel(float* __restrict__ out_mean)
{
    const int row = blockIdx.x;   // b*T + t
    const int b = row >> 11;
    const int t = row & 2047;
    const int len = t + 1;
    const int tid = threadIdx.x;
    const int lane = tid & 31, warp = tid >> 5;

    __shared__ float red[8];

    float accv[8];
#pragma unroll
    for (int i = 0; i < 8; i++) accv[i] = 0.f;

    for (int n = 0; n < NH; n++) {
        const float* Wrow = g_W + ((size_t)(n * B + b) * T + t) * T;
        float v[8];
        float m = -1e30f;
#pragma unroll
        for (int i = 0; i < 8; i++) {
            const int s = tid + i * 256;
            if (s < len) { v[i] = Wrow[s]; m = fmaxf(m, v[i]); }
        }
#pragma unroll
        for (int o = 16; o; o >>= 1) m = fmaxf(m, __shfl_xor_sync(0xffffffffu, m, o));
        if (lane == 0) red[warp] = m;
        __syncthreads();
        m = red[0];
#pragma unroll
        for (int w = 1; w < 8; w++) m = fmaxf(m, red[w]);
        __syncthreads();

        float sum = 0.f;
#pragma unroll
        for (int i = 0; i < 8; i++) {
            const int s = tid + i * 256;
            if (s < len) { v[i] = __expf(v[i] - m); sum += v[i]; }
        }
#pragma unroll
        for (int o = 16; o; o >>= 1) sum += __shfl_xor_sync(0xffffffffu, sum, o);
        if (lane == 0) red[warp] = sum;
        __syncthreads();
        float tot = red[0];
#pragma unroll
        for (int w = 1; w < 8; w++) tot += red[w];
        __syncthreads();

        const float inv = 1.0f / tot;
#pragma unroll
        for (int i = 0; i < 8; i++) {
            const int s = tid + i * 256;
            if (s < len) accv[i] += v[i] * inv;
        }
    }

    float* mrow = out_mean + (size_t)row * T;
#pragma unroll
    for (int i = 0; i < 8; i++) {
        const int s = tid + i * 256;
        mrow[s] = (s < len) ? accv[i] * (1.0f / NH) : 0.f;
    }
}

// ---------------------------------------------------------------------------
// Kernel 5: mean_head = mean_weights @ V (causal, head-mean identity).
// Split over 4 s-chunks into partial buffers. grid = (T/64, B, 4).
// ---------------------------------------------------------------------------
__global__ void av_kernel(const float* __restrict__ mean_w)
{
    const int t_tile = blockIdx.x;
    const int b      = blockIdx.y;
    const int chunk  = blockIdx.z;
    const int t0 = t_tile * 64;

    __shared__ float Ws[64][65];
    __shared__ float Vs[64][65];

    const int tx = threadIdx.x, ty = threadIdx.y;
    const int tid = ty * 16 + tx;

    float acc[4][4];
#pragma unroll
    for (int i = 0; i < 4; i++)
#pragma unroll
        for (int j = 0; j < 4; j++) acc[i][j] = 0.f;

    const int st_begin = chunk * 8;
    const int st_end   = min(chunk * 8 + 8, t_tile + 1);

    for (int st = st_begin; st < st_end; st++) {
        const int s0 = st * 64;
#pragma unroll
        for (int i = 0; i < 16; i++) {
            int idx = tid + i * 256;
            int r = idx >> 6, c = idx & 63;
            Ws[r][c] = mean_w[((size_t)b * T + t0 + r) * T + s0 + c];
            Vs[r][c] = g_V[((size_t)b * T + s0 + r) * D + c];
        }
        __syncthreads();
#pragma unroll 8
        for (int kk = 0; kk < 64; kk++) {
            float a[4], bb[4];
#pragma unroll
            for (int i = 0; i < 4; i++) a[i]  = Ws[ty * 4 + i][kk];
#pragma unroll
            for (int j = 0; j < 4; j++) bb[j] = Vs[kk][tx * 4 + j];
#pragma unroll
            for (int i = 0; i < 4; i++)
#pragma unroll
                for (int j = 0; j < 4; j++) acc[i][j] += a[i] * bb[j];
        }
        __syncthreads();
    }

    float* Cp = g_MHp + (size_t)chunk * B * T * D;
#pragma unroll
    for (int i = 0; i < 4; i++)
#pragma unroll
        for (int j = 0; j < 4; j++)
            Cp[((size_t)b * T + t0 + ty * 4 + i) * D + tx * 4 + j] = acc[i][j];
}

// ---------------------------------------------------------------------------
// Kernel 6: out = (sum of AV partials) @ Wo + bo. grid = (H/64, B*T/64).
// ---------------------------------------------------------------------------
__global__ void out_kernel(const float* __restrict__ Wo,
                           const float* __restrict__ bo,
                           float* __restrict__ out)
{
    const int n0 = blockIdx.x * 64;
    const int m0 = blockIdx.y * 64;

    __shared__ float As[64][65];
    __shared__ float Bs[64][65];

    const int tx = threadIdx.x, ty = threadIdx.y;
    const int tid = ty * 16 + tx;

#pragma unroll
    for (int i = 0; i < 16; i++) {
        int idx = tid + i * 256;
        int r = idx >> 6, c = idx & 63;
        size_t mi = (size_t)(m0 + r) * D + c;
        float v = g_MHp[mi] + g_MHp[(size_t)B * T * D + mi]
                + g_MHp[2 * (size_t)B * T * D + mi]
                + g_MHp[3 * (size_t)B * T * D + mi];
        As[r][c] = v;
        Bs[r][c] = Wo[(size_t)r * H + n0 + c];
    }
    __syncthreads();

    float acc[4][4];
#pragma unroll
    for (int i = 0; i < 4; i++)
#pragma unroll
        for (int j = 0; j < 4; j++) acc[i][j] = 0.f;

#pragma unroll 8
    for (int kk = 0; kk < 64; kk++) {
        float a[4], bb[4];
#pragma unroll
        for (int i = 0; i < 4; i++) a[i]  = As[ty * 4 + i][kk];
#pragma unroll
        for (int j = 0; j < 4; j++) bb[j] = Bs[kk][tx * 4 + j];
#pragma unroll
        for (int i = 0; i < 4; i++)
#pragma unroll
            for (int j = 0; j < 4; j++) acc[i][j] += a[i] * bb[j];
    }

#pragma unroll
    for (int i = 0; i < 4; i++)
#pragma unroll
        for (int j = 0; j < 4; j++)
            out[(size_t)(m0 + ty * 4 + i) * H + n0 + tx * 4 + j] =
                acc[i][j] + bo[n0 + tx * 4 + j];
}

// ---------------------------------------------------------------------------
extern "C" void kernel_launch(void* const* d_in, const int* in_sizes, int n_in,
                              void* d_out, int out_size)
{
    const float* x  = (const float*)d_in[0];
    const float* Wq = (const float*)d_in[1];
    const float* bq = (const float*)d_in[2];
    const float* Wk = (const float*)d_in[3];
    const float* bk = (const float*)d_in[4];
    const float* Wv = (const float*)d_in[5];
    const float* bv = (const float*)d_in[6];
    const float* Wo = (const float*)d_in[7];
    const float* bo = (const float*)d_in[8];

    float* out      = (float*)d_out;                 // [B,T,H]
    float* mean_out = out + (size_t)B * T * H;       // [B,T,T]

    dim3 blk16(16, 16);

    qkproj_tf32       <<<dim3(H / 128, (B * T) / 128, 2), 256>>>(x, Wq, bq, Wk, bk);
    vproj_kernel      <<<(B * T) / 64, blk16>>>(x, Wv, bv);
    scores_tf32       <<<dim3(T / 128, T / 128, NH * B), 256>>>();
    softmax_mean_kernel<<<B * T, 256>>>(mean_out);
    av_kernel         <<<dim3(T / 64, B, 4), blk16>>>(mean_out);
    out_kernel        <<<dim3(H / 64, (B * T) / 64), blk16>>>(Wo, bo, out);
}

// round 4
// speedup vs baseline: 7.0018x; 1.2010x over previous
#include <cuda_runtime.h>
#include <cuda_fp16.h>
#include <cuda_bf16.h>
#include <math.h>
#include <stdint.h>

#define B    2
#define T    2048
#define H    1024
#define NH   16
#define D    64
#define SCALE 0.125f   // D^-0.5

// ---------------- static device scratch (no dynamic allocation allowed) ----
// Q,K layout: [B*T, NH*D] row-major (row = b*T+t, col = n*64+d)
__device__ float  g_Q[(size_t)B * T * H];           // 16 MB
__device__ float  g_K[(size_t)B * T * H];           // 16 MB
__device__ float  g_V[(size_t)B * T * D];           // 1 MB
__device__ __half g_Wh[(size_t)NH * B * T * T];     // 268 MB exp(score) fp16
__device__ float  g_RS[(size_t)NH * B * T * 16];    // 4 MB per-(row,s-tile) exp sums
__device__ float  g_MHp[(size_t)4 * B * T * D];     // 4 MB AV partials

// ---------------------------------------------------------------------------
__device__ __forceinline__ uint32_t f2tf(float f) {
    uint32_t r;
    asm("cvt.rna.tf32.f32 %0, %1;" : "=r"(r) : "f"(f));
    return r;
}

__device__ __forceinline__ void mma_tf32(float* d, const uint32_t* a, const uint32_t* b) {
    asm volatile(
        "mma.sync.aligned.m16n8k8.row.col.f32.tf32.tf32.f32 "
        "{%0,%1,%2,%3}, {%4,%5,%6,%7}, {%8,%9}, {%0,%1,%2,%3};"
        : "+f"(d[0]), "+f"(d[1]), "+f"(d[2]), "+f"(d[3])
        : "r"(a[0]), "r"(a[1]), "r"(a[2]), "r"(a[3]), "r"(b[0]), "r"(b[1]));
}

// ---------------------------------------------------------------------------
// Kernel 1: batched Q/K projection with tf32 tensor cores.
// grid = (8, 32, 2)  z: 0->Q, 1->K
// ---------------------------------------------------------------------------
__global__ void __launch_bounds__(256)
qkproj_tf32(const float* __restrict__ x,
            const float* __restrict__ Wq, const float* __restrict__ bq,
            const float* __restrict__ Wk, const float* __restrict__ bk)
{
    const float* Wm   = blockIdx.z ? Wk : Wq;
    const float* bias = blockIdx.z ? bk : bq;
    float*       C    = blockIdx.z ? g_K : g_Q;
    const int n0 = blockIdx.x * 128;
    const int m0 = blockIdx.y * 128;

    __shared__ uint32_t As[2][128][20];
    __shared__ uint32_t Bs[2][16][136];

    const int tid  = threadIdx.x;
    const int lane = tid & 31;
    const int wid  = tid >> 5;
    const int wm   = wid >> 2;
    const int wn   = wid & 3;
    const int fr   = lane >> 2;
    const int fc   = lane & 3;

    const int am  = tid >> 1;
    const int ak  = (tid & 1) * 8;
    const int bkr = wid;
    const int bn  = lane * 4;
    const int bcol = n0 + bn;
    const size_t bbase = (size_t)(bcol >> 6) * (H * D) + (size_t)(bcol & 63);
    const float* xrow = x + (size_t)(m0 + am) * H + ak;

    float acc[4][4][4];
#pragma unroll
    for (int i = 0; i < 4; i++)
#pragma unroll
        for (int j = 0; j < 4; j++)
#pragma unroll
            for (int q = 0; q < 4; q++) acc[i][j][q] = 0.f;

    float4 ar0, ar1, br0, br1;

    ar0 = *(const float4*)&xrow[0];
    ar1 = *(const float4*)&xrow[4];
    br0 = *(const float4*)&Wm[bbase + (size_t)bkr * D];
    br1 = *(const float4*)&Wm[bbase + (size_t)(bkr + 8) * D];
    {
        uint4 u;
        u.x = f2tf(ar0.x); u.y = f2tf(ar0.y); u.z = f2tf(ar0.z); u.w = f2tf(ar0.w);
        *(uint4*)&As[0][am][ak] = u;
        u.x = f2tf(ar1.x); u.y = f2tf(ar1.y); u.z = f2tf(ar1.z); u.w = f2tf(ar1.w);
        *(uint4*)&As[0][am][ak + 4] = u;
        u.x = f2tf(br0.x); u.y = f2tf(br0.y); u.z = f2tf(br0.z); u.w = f2tf(br0.w);
        *(uint4*)&Bs[0][bkr][bn] = u;
        u.x = f2tf(br1.x); u.y = f2tf(br1.y); u.z = f2tf(br1.z); u.w = f2tf(br1.w);
        *(uint4*)&Bs[0][bkr + 8][bn] = u;
    }
    __syncthreads();

    const int NIT = H / 16;
    for (int it = 0; it < NIT; it++) {
        const int buf = it & 1;
        if (it < NIT - 1) {
            const int k0 = (it + 1) * 16;
            ar0 = *(const float4*)&xrow[k0];
            ar1 = *(const float4*)&xrow[k0 + 4];
            br0 = *(const float4*)&Wm[bbase + (size_t)(k0 + bkr) * D];
            br1 = *(const float4*)&Wm[bbase + (size_t)(k0 + bkr + 8) * D];
        }
#pragma unroll
        for (int ks = 0; ks < 2; ks++) {
            uint32_t af[4][4], bf[4][2];
#pragma unroll
            for (int tm = 0; tm < 4; tm++) {
                const int mb = wm * 64 + tm * 16;
                af[tm][0] = As[buf][mb + fr][ks * 8 + fc];
                af[tm][1] = As[buf][mb + fr + 8][ks * 8 + fc];
                af[tm][2] = As[buf][mb + fr][ks * 8 + fc + 4];
                af[tm][3] = As[buf][mb + fr + 8][ks * 8 + fc + 4];
            }
#pragma unroll
            for (int tn = 0; tn < 4; tn++) {
                const int nb = wn * 32 + tn * 8 + fr;
                bf[tn][0] = Bs[buf][ks * 8 + fc][nb];
                bf[tn][1] = Bs[buf][ks * 8 + fc + 4][nb];
            }
#pragma unroll
            for (int tm = 0; tm < 4; tm++)
#pragma unroll
                for (int tn = 0; tn < 4; tn++)
                    mma_tf32(acc[tm][tn], af[tm], bf[tn]);
        }
        if (it < NIT - 1) {
            const int nb2 = buf ^ 1;
            uint4 u;
            u.x = f2tf(ar0.x); u.y = f2tf(ar0.y); u.z = f2tf(ar0.z); u.w = f2tf(ar0.w);
            *(uint4*)&As[nb2][am][ak] = u;
            u.x = f2tf(ar1.x); u.y = f2tf(ar1.y); u.z = f2tf(ar1.z); u.w = f2tf(ar1.w);
            *(uint4*)&As[nb2][am][ak + 4] = u;
            u.x = f2tf(br0.x); u.y = f2tf(br0.y); u.z = f2tf(br0.z); u.w = f2tf(br0.w);
            *(uint4*)&Bs[nb2][bkr][bn] = u;
            u.x = f2tf(br1.x); u.y = f2tf(br1.y); u.z = f2tf(br1.z); u.w = f2tf(br1.w);
            *(uint4*)&Bs[nb2][bkr + 8][bn] = u;
        }
        __syncthreads();
    }

#pragma unroll
    for (int tm = 0; tm < 4; tm++)
#pragma unroll
        for (int tn = 0; tn < 4; tn++) {
            const int row = m0 + wm * 64 + tm * 16 + fr;
            const int col = n0 + wn * 32 + tn * 8 + 2 * fc;
            const float b0 = bias[col], b1 = bias[col + 1];
            float2 o;
            o.x = acc[tm][tn][0] + b0; o.y = acc[tm][tn][1] + b1;
            *(float2*)&C[(size_t)row * H + col] = o;
            o.x = acc[tm][tn][2] + b0; o.y = acc[tm][tn][3] + b1;
            *(float2*)&C[(size_t)(row + 8) * H + col] = o;
        }
}

// ---------------------------------------------------------------------------
// Kernel 2: V projection (fp32 SIMT, tiny). grid = B*T/64.
// ---------------------------------------------------------------------------
__global__ void vproj_kernel(const float* __restrict__ x,
                             const float* __restrict__ Wv,
                             const float* __restrict__ bv)
{
    const int m0 = blockIdx.x * 64;

    __shared__ float As[64][17];
    __shared__ float Bs[16][65];

    const int tx = threadIdx.x, ty = threadIdx.y;
    const int tid = ty * 16 + tx;

    float acc[4][4];
#pragma unroll
    for (int i = 0; i < 4; i++)
#pragma unroll
        for (int j = 0; j < 4; j++) acc[i][j] = 0.f;

    for (int k0 = 0; k0 < H; k0 += 16) {
#pragma unroll
        for (int i = 0; i < 4; i++) {
            int idx = tid + i * 256;
            int r = idx >> 4, c = idx & 15;
            As[r][c] = x[(size_t)(m0 + r) * H + k0 + c];
        }
#pragma unroll
        for (int i = 0; i < 4; i++) {
            int idx = tid + i * 256;
            int r = idx >> 6, c = idx & 63;
            Bs[r][c] = Wv[(size_t)(k0 + r) * D + c];
        }
        __syncthreads();
#pragma unroll
        for (int kk = 0; kk < 16; kk++) {
            float a[4], bb[4];
#pragma unroll
            for (int i = 0; i < 4; i++) a[i]  = As[ty * 4 + i][kk];
#pragma unroll
            for (int j = 0; j < 4; j++) bb[j] = Bs[kk][tx * 4 + j];
#pragma unroll
            for (int i = 0; i < 4; i++)
#pragma unroll
                for (int j = 0; j < 4; j++) acc[i][j] += a[i] * bb[j];
        }
        __syncthreads();
    }
#pragma unroll
    for (int i = 0; i < 4; i++)
#pragma unroll
        for (int j = 0; j < 4; j++)
            g_V[(size_t)(m0 + ty * 4 + i) * D + tx * 4 + j] =
                acc[i][j] + bv[tx * 4 + j];
}

// ---------------------------------------------------------------------------
// Kernel 3: scores via tf32 mma; epilogue applies exp (no max subtraction:
// |score| <~ 2), masks above-diagonal to exact 0, stores fp16, and emits
// deterministic per-(row, s-tile) sums of exp into g_RS.
// grid = (16, 16, NH*B), z = n*2+b.
// ---------------------------------------------------------------------------
__global__ void __launch_bounds__(256)
scores_tf32()
{
    const int st = blockIdx.x;
    const int tt = blockIdx.y;
    if (st > tt) return;
    const int z = blockIdx.z;
    const int n = z >> 1, b = z & 1;

    const float* Qb = g_Q + (size_t)b * T * H + (size_t)n * D;
    const float* Kb = g_K + (size_t)b * T * H + (size_t)n * D;
    __half*      Wp = g_Wh + (size_t)z * T * T;

    const int t0 = tt * 128, s0 = st * 128;

    __shared__ uint32_t Qs[128][36];
    __shared__ uint32_t Ks[128][36];
    __shared__ float    rs[128][4];

    const int tid  = threadIdx.x;
    const int lane = tid & 31;
    const int wid  = tid >> 5;
    const int wm   = wid >> 2;
    const int wn   = wid & 3;
    const int fr   = lane >> 2;
    const int fc   = lane & 3;

    const int sr = tid >> 1;
    const int sc = (tid & 1) * 16;

    float acc[4][4][4];
#pragma unroll
    for (int i = 0; i < 4; i++)
#pragma unroll
        for (int j = 0; j < 4; j++)
#pragma unroll
            for (int q = 0; q < 4; q++) acc[i][j][q] = 0.f;

    for (int kc = 0; kc < D; kc += 32) {
        if (kc) __syncthreads();
#pragma unroll
        for (int u = 0; u < 4; u++) {
            float4 q4 = *(const float4*)&Qb[(size_t)(t0 + sr) * H + kc + sc + u * 4];
            float4 k4 = *(const float4*)&Kb[(size_t)(s0 + sr) * H + kc + sc + u * 4];
            uint4 uq, uk;
            uq.x = f2tf(q4.x); uq.y = f2tf(q4.y); uq.z = f2tf(q4.z); uq.w = f2tf(q4.w);
            uk.x = f2tf(k4.x); uk.y = f2tf(k4.y); uk.z = f2tf(k4.z); uk.w = f2tf(k4.w);
            *(uint4*)&Qs[sr][sc + u * 4] = uq;
            *(uint4*)&Ks[sr][sc + u * 4] = uk;
        }
        __syncthreads();
#pragma unroll
        for (int ks = 0; ks < 4; ks++) {
            uint32_t af[4][4], bf[4][2];
#pragma unroll
            for (int tm = 0; tm < 4; tm++) {
                const int mb = wm * 64 + tm * 16;
                af[tm][0] = Qs[mb + fr][ks * 8 + fc];
                af[tm][1] = Qs[mb + fr + 8][ks * 8 + fc];
                af[tm][2] = Qs[mb + fr][ks * 8 + fc + 4];
                af[tm][3] = Qs[mb + fr + 8][ks * 8 + fc + 4];
            }
#pragma unroll
            for (int tn = 0; tn < 4; tn++) {
                const int nb = wn * 32 + tn * 8 + fr;
                bf[tn][0] = Ks[nb][ks * 8 + fc];
                bf[tn][1] = Ks[nb][ks * 8 + fc + 4];
            }
#pragma unroll
            for (int tm = 0; tm < 4; tm++)
#pragma unroll
                for (int tn = 0; tn < 4; tn++)
                    mma_tf32(acc[tm][tn], af[tm], bf[tn]);
        }
    }

    // -------- epilogue: exp, causal mask, fp16 store, per-row tile sums ----
    const bool diag = (st == tt);
#pragma unroll
    for (int tm = 0; tm < 4; tm++)
#pragma unroll
        for (int rq = 0; rq < 2; rq++) {
            const int rloc = wm * 64 + tm * 16 + fr + rq * 8;
            const int t = t0 + rloc;
            float rsum = 0.f;
#pragma unroll
            for (int tn = 0; tn < 4; tn++) {
                const int s = s0 + wn * 32 + tn * 8 + 2 * fc;
                float e0 = __expf(acc[tm][tn][rq * 2 + 0] * SCALE);
                float e1 = __expf(acc[tm][tn][rq * 2 + 1] * SCALE);
                if (diag) {
                    if (s     > t) e0 = 0.f;
                    if (s + 1 > t) e1 = 0.f;
                }
                rsum += e0 + e1;
                *(__half2*)&Wp[(size_t)t * T + s] = __floats2half2_rn(e0, e1);
            }
            rsum += __shfl_xor_sync(0xffffffffu, rsum, 1);
            rsum += __shfl_xor_sync(0xffffffffu, rsum, 2);
            if (fc == 0) rs[rloc][wn] = rsum;
        }
    __syncthreads();
    if (tid < 128) {
        float v = rs[tid][0] + rs[tid][1] + rs[tid][2] + rs[tid][3];
        g_RS[((size_t)z * T + t0 + tid) * 16 + st] = v;
    }
}

// ---------------------------------------------------------------------------
// Kernel 4: streaming mean-of-softmax. One block per (b,t), 256 threads.
// No reductions: inv[n] from precomputed tile sums; pure LDG.128 + FMA.
// ---------------------------------------------------------------------------
__global__ void __launch_bounds__(256)
softmax_mean_kernel(float* __restrict__ out_mean)
{
    const int row = blockIdx.x;   // b*T + t
    const int b = row >> 11;
    const int t = row & 2047;
    const int tid = threadIdx.x;

    const int nst = (t >> 7) + 1;     // valid 128-wide s-tiles
    const int L   = nst * 128;

    __shared__ float sinv[NH];
    if (tid < NH) {
        const float* p = g_RS + ((size_t)(tid * B + b) * T + t) * 16;
        float s = 0.f;
        for (int i = 0; i < nst; i++) s += p[i];
        sinv[tid] = (1.0f / NH) / s;
    }
    __syncthreads();

    const int c0 = tid * 8;
    float acc[8];
#pragma unroll
    for (int i = 0; i < 8; i++) acc[i] = 0.f;

    if (c0 < L) {
        const size_t rowoff = ((size_t)b * T + t) * T + c0;
#pragma unroll
        for (int n = 0; n < NH; n++) {
            const __half* p = g_Wh + (size_t)n * (B * (size_t)T * T) + rowoff;
            uint4 u = *(const uint4*)p;
            const float w = sinv[n];
            float2 f;
            f = __half22float2(*(__half2*)&u.x); acc[0] += f.x * w; acc[1] += f.y * w;
            f = __half22float2(*((__half2*)&u.x + 1)); acc[2] += f.x * w; acc[3] += f.y * w;
            f = __half22float2(*(__half2*)&u.z); acc[4] += f.x * w; acc[5] += f.y * w;
            f = __half22float2(*((__half2*)&u.z + 1)); acc[6] += f.x * w; acc[7] += f.y * w;
        }
    }

    float* mrow = out_mean + (size_t)row * T + c0;
    float4 o0 = make_float4(acc[0], acc[1], acc[2], acc[3]);
    float4 o1 = make_float4(acc[4], acc[5], acc[6], acc[7]);
    *(float4*)&mrow[0] = o0;
    *(float4*)&mrow[4] = o1;
}

// ---------------------------------------------------------------------------
// Kernel 5: mean_head = mean_weights @ V (causal, head-mean identity).
// grid = (T/64, B, 4).
// ---------------------------------------------------------------------------
__global__ void av_kernel(const float* __restrict__ mean_w)
{
    const int t_tile = blockIdx.x;
    const int b      = blockIdx.y;
    const int chunk  = blockIdx.z;
    const int t0 = t_tile * 64;

    __shared__ float Ws[64][65];
    __shared__ float Vs[64][65];

    const int tx = threadIdx.x, ty = threadIdx.y;
    const int tid = ty * 16 + tx;

    float acc[4][4];
#pragma unroll
    for (int i = 0; i < 4; i++)
#pragma unroll
        for (int j = 0; j < 4; j++) acc[i][j] = 0.f;

    const int st_begin = chunk * 8;
    const int st_end   = min(chunk * 8 + 8, t_tile + 1);

    for (int st = st_begin; st < st_end; st++) {
        const int s0 = st * 64;
#pragma unroll
        for (int i = 0; i < 16; i++) {
            int idx = tid + i * 256;
            int r = idx >> 6, c = idx & 63;
            Ws[r][c] = mean_w[((size_t)b * T + t0 + r) * T + s0 + c];
            Vs[r][c] = g_V[((size_t)b * T + s0 + r) * D + c];
        }
        __syncthreads();
#pragma unroll 8
        for (int kk = 0; kk < 64; kk++) {
            float a[4], bb[4];
#pragma unroll
            for (int i = 0; i < 4; i++) a[i]  = Ws[ty * 4 + i][kk];
#pragma unroll
            for (int j = 0; j < 4; j++) bb[j] = Vs[kk][tx * 4 + j];
#pragma unroll
            for (int i = 0; i < 4; i++)
#pragma unroll
                for (int j = 0; j < 4; j++) acc[i][j] += a[i] * bb[j];
        }
        __syncthreads();
    }

    float* Cp = g_MHp + (size_t)chunk * B * T * D;
#pragma unroll
    for (int i = 0; i < 4; i++)
#pragma unroll
        for (int j = 0; j < 4; j++)
            Cp[((size_t)b * T + t0 + ty * 4 + i) * D + tx * 4 + j] = acc[i][j];
}

// ---------------------------------------------------------------------------
// Kernel 6: out = (sum of AV partials) @ Wo + bo. grid = (H/64, B*T/64).
// ---------------------------------------------------------------------------
__global__ void out_kernel(const float* __restrict__ Wo,
                           const float* __restrict__ bo,
                           float* __restrict__ out)
{
    const int n0 = blockIdx.x * 64;
    const int m0 = blockIdx.y * 64;

    __shared__ float As[64][65];
    __shared__ float Bs[64][65];

    const int tx = threadIdx.x, ty = threadIdx.y;
    const int tid = ty * 16 + tx;

#pragma unroll
    for (int i = 0; i < 16; i++) {
        int idx = tid + i * 256;
        int r = idx >> 6, c = idx & 63;
        size_t mi = (size_t)(m0 + r) * D + c;
        float v = g_MHp[mi] + g_MHp[(size_t)B * T * D + mi]
                + g_MHp[2 * (size_t)B * T * D + mi]
                + g_MHp[3 * (size_t)B * T * D + mi];
        As[r][c] = v;
        Bs[r][c] = Wo[(size_t)r * H + n0 + c];
    }
    __syncthreads();

    float acc[4][4];
#pragma unroll
    for (int i = 0; i < 4; i++)
#pragma unroll
        for (int j = 0; j < 4; j++) acc[i][j] = 0.f;

#pragma unroll 8
    for (int kk = 0; kk < 64; kk++) {
        float a[4], bb[4];
#pragma unroll
        for (int i = 0; i < 4; i++) a[i]  = As[ty * 4 + i][kk];
#pragma unroll
        for (int j = 0; j < 4; j++) bb[j] = Bs[kk][tx * 4 + j];
#pragma unroll
        for (int i = 0; i < 4; i++)
#pragma unroll
            for (int j = 0; j < 4; j++) acc[i][j] += a[i] * bb[j];
    }

#pragma unroll
    for (int i = 0; i < 4; i++)
#pragma unroll
        for (int j = 0; j < 4; j++)
            out[(size_t)(m0 + ty * 4 + i) * H + n0 + tx * 4 + j] =
                acc[i][j] + bo[n0 + tx * 4 + j];
}

// ---------------------------------------------------------------------------
extern "C" void kernel_launch(void* const* d_in, const int* in_sizes, int n_in,
                              void* d_out, int out_size)
{
    const float* x  = (const float*)d_in[0];
    const float* Wq = (const float*)d_in[1];
    const float* bq = (const float*)d_in[2];
    const float* Wk = (const float*)d_in[3];
    const float* bk = (const float*)d_in[4];
    const float* Wv = (const float*)d_in[5];
    const float* bv = (const float*)d_in[6];
    const float* Wo = (const float*)d_in[7];
    const float* bo = (const float*)d_in[8];

    float* out      = (float*)d_out;                 // [B,T,H]
    float* mean_out = out + (size_t)B * T * H;       // [B,T,T]

    dim3 blk16(16, 16);

    qkproj_tf32        <<<dim3(H / 128, (B * T) / 128, 2), 256>>>(x, Wq, bq, Wk, bk);
    vproj_kernel       <<<(B * T) / 64, blk16>>>(x, Wv, bv);
    scores_tf32        <<<dim3(T / 128, T / 128, NH * B), 256>>>();
    softmax_mean_kernel<<<B * T, 256>>>(mean_out);
    av_kernel          <<<dim3(T / 64, B, 4), blk16>>>(mean_out);
    out_kernel         <<<dim3(H / 64, (B * T) / 64), blk16>>>(Wo, bo, out);
}

// round 6
// speedup vs baseline: 8.7826x; 1.2543x over previous
#include <cuda_runtime.h>
#include <cuda_fp16.h>
#include <cuda_bf16.h>
#include <math.h>
#include <stdint.h>

#define B    2
#define T    2048
#define H    1024
#define NH   16
#define D    64
#define SCALE 0.125f   // D^-0.5

// ---------------- static device scratch (no dynamic allocation allowed) ----
// Q,K layout: [B*T, NH*D] row-major bf16 (row = b*T+t, col = n*64+d)
__device__ __nv_bfloat16 g_Qh[(size_t)B * T * H];   // 8 MB
__device__ __nv_bfloat16 g_Kh[(size_t)B * T * H];   // 8 MB
__device__ float  g_V[(size_t)B * T * D];           // 1 MB
__device__ __half g_Wh[(size_t)NH * B * T * T];     // 268 MB exp(score) fp16
__device__ float  g_RS[(size_t)NH * B * T * 16];    // 4 MB per-(row,s-tile) exp sums
__device__ float  g_MHp[(size_t)4 * B * T * D];     // 4 MB AV partials

// ---------------------------------------------------------------------------
__device__ __forceinline__ uint32_t pack_bf2(float lo, float hi) {
    __nv_bfloat162 h = __floats2bfloat162_rn(lo, hi);
    return *(uint32_t*)&h;
}

__device__ __forceinline__ void mma_bf16(float* d, const uint32_t* a, const uint32_t* b) {
    asm volatile(
        "mma.sync.aligned.m16n8k16.row.col.f32.bf16.bf16.f32 "
        "{%0,%1,%2,%3}, {%4,%5,%6,%7}, {%8,%9}, {%0,%1,%2,%3};"
        : "+f"(d[0]), "+f"(d[1]), "+f"(d[2]), "+f"(d[3])
        : "r"(a[0]), "r"(a[1]), "r"(a[2]), "r"(a[3]), "r"(b[0]), "r"(b[1]));
}

// ---------------------------------------------------------------------------
// Kernel 1: batched Q/K projection, bf16 tensor cores, fp32 accumulate.
// C[4096,1024] = x @ Wbig + bias, Wbig(h,col)=W[(col>>6)*H*D + h*64 + (col&63)].
// 128x128 CTA tile, 8 warps (2m x 4n), warp tile 64x32, BK=32, double buffered.
// Output stored as bf16. grid = (8, 32, 2)  z: 0->Q, 1->K
// ---------------------------------------------------------------------------
__global__ void __launch_bounds__(256)
qkproj_bf16(const float* __restrict__ x,
            const float* __restrict__ Wq, const float* __restrict__ bq,
            const float* __restrict__ Wk, const float* __restrict__ bk)
{
    const float* Wm    = blockIdx.z ? Wk : Wq;
    const float* bias  = blockIdx.z ? bk : bq;
    __nv_bfloat16* C   = blockIdx.z ? g_Kh : g_Qh;
    const int n0 = blockIdx.x * 128;
    const int m0 = blockIdx.y * 128;

    // word = bf16x2 (k-pair). As2: [m][kpair] pitch 20; Bs2: [kpair][n] pitch 136.
    __shared__ __align__(16) uint32_t As2[2][128][20];
    __shared__ __align__(16) uint32_t Bs2[2][16][136];

    const int tid  = threadIdx.x;
    const int lane = tid & 31;
    const int wid  = tid >> 5;
    const int wm   = wid >> 2;          // 0..1
    const int wn   = wid & 3;           // 0..3
    const int fr   = lane >> 2;         // 0..7
    const int fc   = lane & 3;          // 0..3

    // A staging: row am, 16 k-values starting at ak
    const int am = tid >> 1;
    const int ak = (tid & 1) * 16;
    const float* xrow = x + (size_t)(m0 + am) * H + ak;
    // B staging: k-pair p (rows 2p,2p+1), 8 cols starting at nn
    const int p  = tid >> 4;            // 0..15
    const int nn = (tid & 15) * 8;      // 0..120
    const int bcol = n0 + nn;
    const size_t bbase = (size_t)(bcol >> 6) * (H * D) + (size_t)(bcol & 63);

    float acc[4][4][4];
#pragma unroll
    for (int i = 0; i < 4; i++)
#pragma unroll
        for (int j = 0; j < 4; j++)
#pragma unroll
            for (int q = 0; q < 4; q++) acc[i][j][q] = 0.f;

    float4 a0, a1, a2, a3, blo0, blo1, bhi0, bhi1;

    // prologue: load iter 0 (k0 = 0)
    a0 = *(const float4*)&xrow[0];
    a1 = *(const float4*)&xrow[4];
    a2 = *(const float4*)&xrow[8];
    a3 = *(const float4*)&xrow[12];
    blo0 = *(const float4*)&Wm[bbase + (size_t)(2 * p)     * D];
    blo1 = *(const float4*)&Wm[bbase + (size_t)(2 * p)     * D + 4];
    bhi0 = *(const float4*)&Wm[bbase + (size_t)(2 * p + 1) * D];
    bhi1 = *(const float4*)&Wm[bbase + (size_t)(2 * p + 1) * D + 4];
    {
        uint4 u;
        u.x = pack_bf2(a0.x, a0.y); u.y = pack_bf2(a0.z, a0.w);
        u.z = pack_bf2(a1.x, a1.y); u.w = pack_bf2(a1.z, a1.w);
        *(uint4*)&As2[0][am][ak / 2] = u;
        u.x = pack_bf2(a2.x, a2.y); u.y = pack_bf2(a2.z, a2.w);
        u.z = pack_bf2(a3.x, a3.y); u.w = pack_bf2(a3.z, a3.w);
        *(uint4*)&As2[0][am][ak / 2 + 4] = u;
        u.x = pack_bf2(blo0.x, bhi0.x); u.y = pack_bf2(blo0.y, bhi0.y);
        u.z = pack_bf2(blo0.z, bhi0.z); u.w = pack_bf2(blo0.w, bhi0.w);
        *(uint4*)&Bs2[0][p][nn] = u;
        u.x = pack_bf2(blo1.x, bhi1.x); u.y = pack_bf2(blo1.y, bhi1.y);
        u.z = pack_bf2(blo1.z, bhi1.z); u.w = pack_bf2(blo1.w, bhi1.w);
        *(uint4*)&Bs2[0][p][nn + 4] = u;
    }
    __syncthreads();

    const int NIT = H / 32;   // 32
    for (int it = 0; it < NIT; it++) {
        const int buf = it & 1;
        if (it < NIT - 1) {
            const int k0 = (it + 1) * 32;
            a0 = *(const float4*)&xrow[k0];
            a1 = *(const float4*)&xrow[k0 + 4];
            a2 = *(const float4*)&xrow[k0 + 8];
            a3 = *(const float4*)&xrow[k0 + 12];
            blo0 = *(const float4*)&Wm[bbase + (size_t)(k0 + 2 * p)     * D];
            blo1 = *(const float4*)&Wm[bbase + (size_t)(k0 + 2 * p)     * D + 4];
            bhi0 = *(const float4*)&Wm[bbase + (size_t)(k0 + 2 * p + 1) * D];
            bhi1 = *(const float4*)&Wm[bbase + (size_t)(k0 + 2 * p + 1) * D + 4];
        }
#pragma unroll
        for (int ks = 0; ks < 2; ks++) {     // two k16 chunks per stage
            uint32_t af[4][4], bf[4][2];
#pragma unroll
            for (int tm = 0; tm < 4; tm++) {
                const int mb = wm * 64 + tm * 16;
                af[tm][0] = As2[buf][mb + fr][ks * 8 + fc];
                af[tm][1] = As2[buf][mb + fr + 8][ks * 8 + fc];
                af[tm][2] = As2[buf][mb + fr][ks * 8 + fc + 4];
                af[tm][3] = As2[buf][mb + fr + 8][ks * 8 + fc + 4];
            }
#pragma unroll
            for (int tn = 0; tn < 4; tn++) {
                const int nb = wn * 32 + tn * 8 + fr;
                bf[tn][0] = Bs2[buf][ks * 8 + fc][nb];
                bf[tn][1] = Bs2[buf][ks * 8 + fc + 4][nb];
            }
#pragma unroll
            for (int tm = 0; tm < 4; tm++)
#pragma unroll
                for (int tn = 0; tn < 4; tn++)
                    mma_bf16(acc[tm][tn], af[tm], bf[tn]);
        }
        if (it < NIT - 1) {
            const int nb2 = (it & 1) ^ 1;
            uint4 u;
            u.x = pack_bf2(a0.x, a0.y); u.y = pack_bf2(a0.z, a0.w);
            u.z = pack_bf2(a1.x, a1.y); u.w = pack_bf2(a1.z, a1.w);
            *(uint4*)&As2[nb2][am][ak / 2] = u;
            u.x = pack_bf2(a2.x, a2.y); u.y = pack_bf2(a2.z, a2.w);
            u.z = pack_bf2(a3.x, a3.y); u.w = pack_bf2(a3.z, a3.w);
            *(uint4*)&As2[nb2][am][ak / 2 + 4] = u;
            u.x = pack_bf2(blo0.x, bhi0.x); u.y = pack_bf2(blo0.y, bhi0.y);
            u.z = pack_bf2(blo0.z, bhi0.z); u.w = pack_bf2(blo0.w, bhi0.w);
            *(uint4*)&Bs2[nb2][p][nn] = u;
            u.x = pack_bf2(blo1.x, bhi1.x); u.y = pack_bf2(blo1.y, bhi1.y);
            u.z = pack_bf2(blo1.z, bhi1.z); u.w = pack_bf2(blo1.w, bhi1.w);
            *(uint4*)&Bs2[nb2][p][nn + 4] = u;
        }
        __syncthreads();
    }

#pragma unroll
    for (int tm = 0; tm < 4; tm++)
#pragma unroll
        for (int tn = 0; tn < 4; tn++) {
            const int row = m0 + wm * 64 + tm * 16 + fr;
            const int col = n0 + wn * 32 + tn * 8 + 2 * fc;
            const float b0 = bias[col], b1 = bias[col + 1];
            __nv_bfloat162 o;
            o = __floats2bfloat162_rn(acc[tm][tn][0] + b0, acc[tm][tn][1] + b1);
            *(__nv_bfloat162*)&C[(size_t)row * H + col] = o;
            o = __floats2bfloat162_rn(acc[tm][tn][2] + b0, acc[tm][tn][3] + b1);
            *(__nv_bfloat162*)&C[(size_t)(row + 8) * H + col] = o;
        }
}

// ---------------------------------------------------------------------------
// Kernel 2: V projection (fp32 SIMT — precision matters for `out`).
// ---------------------------------------------------------------------------
__global__ void vproj_kernel(const float* __restrict__ x,
                             const float* __restrict__ Wv,
                             const float* __restrict__ bv)
{
    const int m0 = blockIdx.x * 64;

    __shared__ float As[64][17];
    __shared__ float Bs[16][65];

    const int tx = threadIdx.x, ty = threadIdx.y;
    const int tid = ty * 16 + tx;

    float acc[4][4];
#pragma unroll
    for (int i = 0; i < 4; i++)
#pragma unroll
        for (int j = 0; j < 4; j++) acc[i][j] = 0.f;

    for (int k0 = 0; k0 < H; k0 += 16) {
#pragma unroll
        for (int i = 0; i < 4; i++) {
            int idx = tid + i * 256;
            int r = idx >> 4, c = idx & 15;
            As[r][c] = x[(size_t)(m0 + r) * H + k0 + c];
        }
#pragma unroll
        for (int i = 0; i < 4; i++) {
            int idx = tid + i * 256;
            int r = idx >> 6, c = idx & 63;
            Bs[r][c] = Wv[(size_t)(k0 + r) * D + c];
        }
        __syncthreads();
#pragma unroll
        for (int kk = 0; kk < 16; kk++) {
            float a[4], bb[4];
#pragma unroll
            for (int i = 0; i < 4; i++) a[i]  = As[ty * 4 + i][kk];
#pragma unroll
            for (int j = 0; j < 4; j++) bb[j] = Bs[kk][tx * 4 + j];
#pragma unroll
            for (int i = 0; i < 4; i++)
#pragma unroll
                for (int j = 0; j < 4; j++) acc[i][j] += a[i] * bb[j];
        }
        __syncthreads();
    }
#pragma unroll
    for (int i = 0; i < 4; i++)
#pragma unroll
        for (int j = 0; j < 4; j++)
            g_V[(size_t)(m0 + ty * 4 + i) * D + tx * 4 + j] =
                acc[i][j] + bv[tx * 4 + j];
}

// ---------------------------------------------------------------------------
// Kernel 3: scores via bf16 mma (causal 128-tiles only). Epilogue: exp (no
// max subtraction, |score| small), exact-zero above diagonal, fp16 store,
// deterministic per-(row, s-tile) exp sums. grid = (16,16,NH*B), z = n*2+b.
// ---------------------------------------------------------------------------
__global__ void __launch_bounds__(256)
scores_bf16()
{
    const int st = blockIdx.x;
    const int tt = blockIdx.y;
    if (st > tt) return;
    const int z = blockIdx.z;
    const int n = z >> 1, b = z & 1;

    const __nv_bfloat16* Qb = g_Qh + (size_t)b * T * H + (size_t)n * D;
    const __nv_bfloat16* Kb = g_Kh + (size_t)b * T * H + (size_t)n * D;
    __half* Wp = g_Wh + (size_t)z * T * T;

    const int t0 = tt * 128, s0 = st * 128;

    // word = bf16x2 d-pair; pitch 36 -> conflict-free fragment LDS
    __shared__ __align__(16) uint32_t Qs2[128][36];
    __shared__ __align__(16) uint32_t Ks2[128][36];
    __shared__ float rs[128][4];

    const int tid  = threadIdx.x;
    const int lane = tid & 31;
    const int wid  = tid >> 5;
    const int wm   = wid >> 2;
    const int wn   = wid & 3;
    const int fr   = lane >> 2;
    const int fc   = lane & 3;

    // staging: row sr, 32 bf16 starting at sc
    const int sr = tid >> 1;
    const int sc = (tid & 1) * 32;
#pragma unroll
    for (int u = 0; u < 4; u++) {
        uint4 q4 = *(const uint4*)&Qb[(size_t)(t0 + sr) * H + sc + u * 8];
        uint4 k4 = *(const uint4*)&Kb[(size_t)(s0 + sr) * H + sc + u * 8];
        *(uint4*)&Qs2[sr][sc / 2 + u * 4] = q4;
        *(uint4*)&Ks2[sr][sc / 2 + u * 4] = k4;
    }
    __syncthreads();

    float acc[4][4][4];
#pragma unroll
    for (int i = 0; i < 4; i++)
#pragma unroll
        for (int j = 0; j < 4; j++)
#pragma unroll
            for (int q = 0; q < 4; q++) acc[i][j][q] = 0.f;

#pragma unroll
    for (int ks = 0; ks < 4; ks++) {     // 4 x k16 = D=64
        uint32_t af[4][4], bf[4][2];
#pragma unroll
        for (int tm = 0; tm < 4; tm++) {
            const int mb = wm * 64 + tm * 16;
            af[tm][0] = Qs2[mb + fr][ks * 8 + fc];
            af[tm][1] = Qs2[mb + fr + 8][ks * 8 + fc];
            af[tm][2] = Qs2[mb + fr][ks * 8 + fc + 4];
            af[tm][3] = Qs2[mb + fr + 8][ks * 8 + fc + 4];
        }
#pragma unroll
        for (int tn = 0; tn < 4; tn++) {
            const int nb = wn * 32 + tn * 8 + fr;
            bf[tn][0] = Ks2[nb][ks * 8 + fc];
            bf[tn][1] = Ks2[nb][ks * 8 + fc + 4];
        }
#pragma unroll
        for (int tm = 0; tm < 4; tm++)
#pragma unroll
            for (int tn = 0; tn < 4; tn++)
                mma_bf16(acc[tm][tn], af[tm], bf[tn]);
    }

    // -------- epilogue: exp, causal mask, fp16 store, per-row tile sums ----
    const bool diag = (st == tt);
#pragma unroll
    for (int tm = 0; tm < 4; tm++)
#pragma unroll
        for (int rq = 0; rq < 2; rq++) {
            const int rloc = wm * 64 + tm * 16 + fr + rq * 8;
            const int t = t0 + rloc;
            float rsum = 0.f;
#pragma unroll
            for (int tn = 0; tn < 4; tn++) {
                const int s = s0 + wn * 32 + tn * 8 + 2 * fc;
                float e0 = __expf(acc[tm][tn][rq * 2 + 0] * SCALE);
                float e1 = __expf(acc[tm][tn][rq * 2 + 1] * SCALE);
                if (diag) {
                    if (s     > t) e0 = 0.f;
                    if (s + 1 > t) e1 = 0.f;
                }
                rsum += e0 + e1;
                *(__half2*)&Wp[(size_t)t * T + s] = __floats2half2_rn(e0, e1);
            }
            rsum += __shfl_xor_sync(0xffffffffu, rsum, 1);
            rsum += __shfl_xor_sync(0xffffffffu, rsum, 2);
            if (fc == 0) rs[rloc][wn] = rsum;
        }
    __syncthreads();
    if (tid < 128) {
        float v = rs[tid][0] + rs[tid][1] + rs[tid][2] + rs[tid][3];
        g_RS[((size_t)z * T + t0 + tid) * 16 + st] = v;
    }
}

// ---------------------------------------------------------------------------
// Kernel 4: streaming mean-of-softmax. One block per (b,t), 256 threads.
// ---------------------------------------------------------------------------
__global__ void __launch_bounds__(256)
softmax_mean_kernel(float* __restrict__ out_mean)
{
    const int row = blockIdx.x;   // b*T + t
    const int b = row >> 11;
    const int t = row & 2047;
    const int tid = threadIdx.x;

    const int nst = (t >> 7) + 1;
    const int L   = nst * 128;

    __shared__ float sinv[NH];
    if (tid < NH) {
        const float* p = g_RS + ((size_t)(tid * B + b) * T + t) * 16;
        float s = 0.f;
        for (int i = 0; i < nst; i++) s += p[i];
        sinv[tid] = (1.0f / NH) / s;
    }
    __syncthreads();

    const int c0 = tid * 8;
    float acc[8];
#pragma unroll
    for (int i = 0; i < 8; i++) acc[i] = 0.f;

    if (c0 < L) {
        const size_t rowoff = ((size_t)b * T + t) * T + c0;
#pragma unroll
        for (int n = 0; n < NH; n++) {
            const __half* p = g_Wh + (size_t)n * (B * (size_t)T * T) + rowoff;
            uint4 u = *(const uint4*)p;
            const float w = sinv[n];
            float2 f;
            f = __half22float2(*(__half2*)&u.x); acc[0] += f.x * w; acc[1] += f.y * w;
            f = __half22float2(*((__half2*)&u.x + 1)); acc[2] += f.x * w; acc[3] += f.y * w;
            f = __half22float2(*(__half2*)&u.z); acc[4] += f.x * w; acc[5] += f.y * w;
            f = __half22float2(*((__half2*)&u.z + 1)); acc[6] += f.x * w; acc[7] += f.y * w;
        }
    }

    float* mrow = out_mean + (size_t)row * T + c0;
    *(float4*)&mrow[0] = make_float4(acc[0], acc[1], acc[2], acc[3]);
    *(float4*)&mrow[4] = make_float4(acc[4], acc[5], acc[6], acc[7]);
}

// ---------------------------------------------------------------------------
// Kernel 5: mean_head = mean_weights @ V (head-mean identity, causal).
// grid = (T/64, B, 4).
// ---------------------------------------------------------------------------
__global__ void av_kernel(const float* __restrict__ mean_w)
{
    const int t_tile = blockIdx.x;
    const int b      = blockIdx.y;
    const int chunk  = blockIdx.z;
    const int t0 = t_tile * 64;

    __shared__ float Ws[64][65];
    __shared__ float Vs[64][65];

    const int tx = threadIdx.x, ty = threadIdx.y;
    const int tid = ty * 16 + tx;

    float acc[4][4];
#pragma unroll
    for (int i = 0; i < 4; i++)
#pragma unroll
        for (int j = 0; j < 4; j++) acc[i][j] = 0.f;

    const int st_begin = chunk * 8;
    const int st_end   = min(chunk * 8 + 8, t_tile + 1);

    for (int st = st_begin; st < st_end; st++) {
        const int s0 = st * 64;
#pragma unroll
        for (int i = 0; i < 16; i++) {
            int idx = tid + i * 256;
            int r = idx >> 6, c = idx & 63;
            Ws[r][c] = mean_w[((size_t)b * T + t0 + r) * T + s0 + c];
            Vs[r][c] = g_V[((size_t)b * T + s0 + r) * D + c];
        }
        __syncthreads();
#pragma unroll 8
        for (int kk = 0; kk < 64; kk++) {
            float a[4], bb[4];
#pragma unroll
            for (int i = 0; i < 4; i++) a[i]  = Ws[ty * 4 + i][kk];
#pragma unroll
            for (int j = 0; j < 4; j++) bb[j] = Vs[kk][tx * 4 + j];
#pragma unroll
            for (int i = 0; i < 4; i++)
#pragma unroll
                for (int j = 0; j < 4; j++) acc[i][j] += a[i] * bb[j];
        }
        __syncthreads();
    }

    float* Cp = g_MHp + (size_t)chunk * B * T * D;
#pragma unroll
    for (int i = 0; i < 4; i++)
#pragma unroll
        for (int j = 0; j < 4; j++)
            Cp[((size_t)b * T + t0 + ty * 4 + i) * D + tx * 4 + j] = acc[i][j];
}

// ---------------------------------------------------------------------------
// Kernel 6: out = (sum of AV partials) @ Wo + bo. grid = (H/64, B*T/64).
// ---------------------------------------------------------------------------
__global__ void out_kernel(const float* __restrict__ Wo,
                           const float* __restrict__ bo,
                           float* __restrict__ out)
{
    const int n0 = blockIdx.x * 64;
    const int m0 = blockIdx.y * 64;

    __shared__ float As[64][65];
    __shared__ float Bs[64][65];

    const int tx = threadIdx.x, ty = threadIdx.y;
    const int tid = ty * 16 + tx;

#pragma unroll
    for (int i = 0; i < 16; i++) {
        int idx = tid + i * 256;
        int r = idx >> 6, c = idx & 63;
        size_t mi = (size_t)(m0 + r) * D + c;
        float v = g_MHp[mi] + g_MHp[(size_t)B * T * D + mi]
                + g_MHp[2 * (size_t)B * T * D + mi]
                + g_MHp[3 * (size_t)B * T * D + mi];
        As[r][c] = v;
        Bs[r][c] = Wo[(size_t)r * H + n0 + c];
    }
    __syncthreads();

    float acc[4][4];
#pragma unroll
    for (int i = 0; i < 4; i++)
#pragma unroll
        for (int j = 0; j < 4; j++) acc[i][j] = 0.f;

#pragma unroll 8
    for (int kk = 0; kk < 64; kk++) {
        float a[4], bb[4];
#pragma unroll
        for (int i = 0; i < 4; i++) a[i]  = As[ty * 4 + i][kk];
#pragma unroll
        for (int j = 0; j < 4; j++) bb[j] = Bs[kk][tx * 4 + j];
#pragma unroll
        for (int i = 0; i < 4; i++)
#pragma unroll
            for (int j = 0; j < 4; j++) acc[i][j] += a[i] * bb[j];
    }

#pragma unroll
    for (int i = 0; i < 4; i++)
#pragma unroll
        for (int j = 0; j < 4; j++)
            out[(size_t)(m0 + ty * 4 + i) * H + n0 + tx * 4 + j] =
                acc[i][j] + bo[n0 + tx * 4 + j];
}

// ---------------------------------------------------------------------------
extern "C" void kernel_launch(void* const* d_in, const int* in_sizes, int n_in,
                              void* d_out, int out_size)
{
    const float* x  = (const float*)d_in[0];
    const float* Wq = (const float*)d_in[1];
    const float* bq = (const float*)d_in[2];
    const float* Wk = (const float*)d_in[3];
    const float* bk = (const float*)d_in[4];
    const float* Wv = (const float*)d_in[5];
    const float* bv = (const float*)d_in[6];
    const float* Wo = (const float*)d_in[7];
    const float* bo = (const float*)d_in[8];

    float* out      = (float*)d_out;                 // [B,T,H]
    float* mean_out = out + (size_t)B * T * H;       // [B,T,T]

    dim3 blk16(16, 16);

    qkproj_bf16        <<<dim3(H / 128, (B * T) / 128, 2), 256>>>(x, Wq, bq, Wk, bk);
    vproj_kernel       <<<(B * T) / 64, blk16>>>(x, Wv, bv);
    scores_bf16        <<<dim3(T / 128, T / 128, NH * B), 256>>>();
    softmax_mean_kernel<<<B * T, 256>>>(mean_out);
    av_kernel          <<<dim3(T / 64, B, 4), blk16>>>(mean_out);
    out_kernel         <<<dim3(H / 64, (B * T) / 64), blk16>>>(Wo, bo, out);
}